// round 1
// baseline (speedup 1.0000x reference)
#include <cuda_runtime.h>
#include <math_constants.h>

#define BB 4
#define GRID_N 196
#define DM 512
#define NH 8
#define DK 64
#define ROWS (BB * GRID_N)   // 784

// ---- scratch (no allocations allowed) ----
__device__ float g_qsig[ROWS * DM];
__device__ float g_kp[ROWS * DM];
__device__ float g_vp[ROWS * DM];
__device__ float g_img[ROWS * DM];

__device__ __forceinline__ float sigm(float x) {
    // accurate: 1/(1+e^-x) via MUFU.EX2 + MUFU.RCP
    return __fdividef(1.0f, 1.0f + __expf(-x));
}

// ============================================================
// GEMM: out[r, j] = sum_c X[r, c] * W[j, c] + bias[j]
// EPILOGUE 0: plain (projections)
// EPILOGUE 1: o = acc + b;  out = o * sigmoid(qsig[r,j] * o)
// Tile 64x64, K-chunk 16, 256 threads, 4x4 micro-tile.
// ============================================================
template <int EPILOGUE>
__global__ void __launch_bounds__(256)
gemm_kernel(const float* __restrict__ X,
            const float* __restrict__ W,
            const float* __restrict__ bias,
            float* __restrict__ out,
            const float* __restrict__ qsig) {
    __shared__ float As[16][68];
    __shared__ float Bs[16][68];

    const int t  = threadIdx.x;
    const int tx = t & 15;          // n-dir
    const int ty = t >> 4;          // m-dir
    const int r0 = blockIdx.x * 64;
    const int j0 = blockIdx.y * 64;

    const int lrow = t >> 2;        // 0..63
    const int c4   = (t & 3) << 2;  // 0,4,8,12

    float acc[4][4];
#pragma unroll
    for (int i = 0; i < 4; i++)
#pragma unroll
        for (int j = 0; j < 4; j++) acc[i][j] = 0.0f;

    for (int kc = 0; kc < DM; kc += 16) {
        float4 xv = make_float4(0.f, 0.f, 0.f, 0.f);
        const int gr = r0 + lrow;
        if (gr < ROWS) xv = *(const float4*)&X[gr * DM + kc + c4];
        const float4 wv = *(const float4*)&W[(j0 + lrow) * DM + kc + c4];
        As[c4 + 0][lrow] = xv.x; As[c4 + 1][lrow] = xv.y;
        As[c4 + 2][lrow] = xv.z; As[c4 + 3][lrow] = xv.w;
        Bs[c4 + 0][lrow] = wv.x; Bs[c4 + 1][lrow] = wv.y;
        Bs[c4 + 2][lrow] = wv.z; Bs[c4 + 3][lrow] = wv.w;
        __syncthreads();
#pragma unroll
        for (int kk = 0; kk < 16; kk++) {
            const float4 a = *(const float4*)&As[kk][ty << 2];
            const float4 b = *(const float4*)&Bs[kk][tx << 2];
            const float av[4] = {a.x, a.y, a.z, a.w};
            const float bv[4] = {b.x, b.y, b.z, b.w};
#pragma unroll
            for (int i = 0; i < 4; i++)
#pragma unroll
                for (int j = 0; j < 4; j++)
                    acc[i][j] = fmaf(av[i], bv[j], acc[i][j]);
        }
        __syncthreads();
    }

    const int jc = j0 + (tx << 2);
    const float4 bv4 = *(const float4*)&bias[jc];
#pragma unroll
    for (int i = 0; i < 4; i++) {
        const int r = r0 + (ty << 2) + i;
        if (r >= ROWS) continue;
        float4 o;
        o.x = acc[i][0] + bv4.x;
        o.y = acc[i][1] + bv4.y;
        o.z = acc[i][2] + bv4.z;
        o.w = acc[i][3] + bv4.w;
        if (EPILOGUE == 1) {
            const float4 q = *(const float4*)&qsig[r * DM + jc];
            o.x *= sigm(q.x * o.x);
            o.y *= sigm(q.y * o.y);
            o.z *= sigm(q.z * o.z);
            o.w *= sigm(q.w * o.w);
        }
        *(float4*)&out[r * DM + jc] = o;
    }
}

// ============================================================
// Fused attention core.
// block = (b, h, q-tile of 8); 256 threads; warp w handles q = qt*8+w.
// smem: K,V head slices (196x64, row stride 66 floats), q rows, p rows.
//   image[b,h,q,d] = sum_k p[q,k] * sigmoid(q_sig[q,d]*k_p[k,d]) * v_p[k,d]
// ============================================================
#define KST 66
#define KROWS 224   // 196 padded to 7*32 so pass-1 lane indexing never leaves the array
#define ATTN_SMEM_FLOATS (2 * KROWS * KST + 8 * 64 + 8 * 200)

__global__ void __launch_bounds__(256)
attn_kernel(const float* __restrict__ scale) {
    extern __shared__ float sm[];
    float* kp = sm;
    float* vp = kp + KROWS * KST;
    float* qs = vp + KROWS * KST;
    float* ps = qs + 8 * 64;

    const int t  = threadIdx.x;
    const int qt = blockIdx.x;   // 0..24
    const int h  = blockIdx.y;
    const int b  = blockIdx.z;
    const int hbase = h * DK;

    // ---- load K,V head slices into smem (float4 global reads) ----
    for (int idx = t; idx < GRID_N * 16; idx += 256) {
        const int s  = idx >> 4;
        const int d4 = (idx & 15) << 2;
        const int g  = (b * GRID_N + s) * DM + hbase + d4;
        const float4 kv = *(const float4*)&g_kp[g];
        const float4 vv = *(const float4*)&g_vp[g];
        float* kd = &kp[s * KST + d4];
        kd[0] = kv.x; kd[1] = kv.y; kd[2] = kv.z; kd[3] = kv.w;
        float* vd = &vp[s * KST + d4];
        vd[0] = vv.x; vd[1] = vv.y; vd[2] = vv.z; vd[3] = vv.w;
    }
    // zero the pad rows of kp (read by pass-1 lanes with k>=196, masked later)
    for (int idx = t; idx < (KROWS - GRID_N) * KST; idx += 256)
        kp[GRID_N * KST + idx] = 0.0f;
    // ---- load q rows ----
    for (int idx = t; idx < 8 * 64; idx += 256) {
        const int w = idx >> 6;
        const int d = idx & 63;
        const int q = qt * 8 + w;
        qs[idx] = (q < GRID_N) ? g_qsig[(b * GRID_N + q) * DM + hbase + d] : 0.0f;
    }
    __syncthreads();

    const int w    = t >> 5;
    const int lane = t & 31;
    const int q    = qt * 8 + w;
    if (q >= GRID_N) return;

    const float* qrow = &qs[w * 64];

    // ---- pass 1: att[k] = scale * <q_row, k_row> ; lanes over k ----
    float att[7];
#pragma unroll
    for (int j = 0; j < 7; j++) att[j] = 0.0f;

#pragma unroll 8
    for (int d = 0; d < 64; d += 2) {
        const float2 qd = *(const float2*)&qrow[d];
#pragma unroll
        for (int j = 0; j < 7; j++) {
            const float2 kv = *(const float2*)&kp[(lane + 32 * j) * KST + d];
            att[j] = fmaf(qd.x, kv.x, fmaf(qd.y, kv.y, att[j]));
        }
    }
    const float* srow = &scale[(h * GRID_N + q) * GRID_N];
#pragma unroll
    for (int j = 0; j < 7; j++) {
        const int k = lane + 32 * j;
        att[j] = (k < GRID_N) ? att[j] * srow[k] : -CUDART_INF_F;
    }

    // ---- warp softmax over 196 k ----
    float m = att[0];
#pragma unroll
    for (int j = 1; j < 7; j++) m = fmaxf(m, att[j]);
#pragma unroll
    for (int off = 16; off > 0; off >>= 1)
        m = fmaxf(m, __shfl_xor_sync(0xFFFFFFFFu, m, off));
    float ssum = 0.0f;
#pragma unroll
    for (int j = 0; j < 7; j++) {
        att[j] = __expf(att[j] - m);   // exp(-inf)=0 masks pad k
        ssum += att[j];
    }
#pragma unroll
    for (int off = 16; off > 0; off >>= 1)
        ssum += __shfl_xor_sync(0xFFFFFFFFu, ssum, off);
    const float inv = __fdividef(1.0f, ssum);
    float* pw = &ps[w * 200];
#pragma unroll
    for (int j = 0; j < 7; j++) {
        const int k = lane + 32 * j;
        if (k < GRID_N) pw[k] = att[j] * inv;
    }
    __syncwarp();

    // ---- pass 2: sigmoid-gated PV ; lanes over d (2 per lane) ----
    const float nq0 = -qrow[2 * lane];
    const float nq1 = -qrow[2 * lane + 1];
    float accx = 0.0f, accy = 0.0f;
#pragma unroll 4
    for (int k = 0; k < GRID_N; k++) {
        const float  pk = pw[k];
        const float2 kv = *(const float2*)&kp[k * KST + 2 * lane];
        const float2 vv = *(const float2*)&vp[k * KST + 2 * lane];
        const float s0 = __fdividef(1.0f, 1.0f + __expf(nq0 * kv.x));
        const float s1 = __fdividef(1.0f, 1.0f + __expf(nq1 * kv.y));
        accx = fmaf(pk, s0 * vv.x, accx);
        accy = fmaf(pk, s1 * vv.y, accy);
    }
    float2 r;
    r.x = accx;
    r.y = accy;
    *(float2*)&g_img[(b * GRID_N + q) * DM + hbase + 2 * lane] = r;
}

// ============================================================
extern "C" void kernel_launch(void* const* d_in, const int* in_sizes, int n_in,
                              void* d_out, int out_size) {
    (void)in_sizes; (void)n_in; (void)out_size;
    const float* queries = (const float*)d_in[0];
    const float* keys    = (const float*)d_in[1];
    const float* values  = (const float*)d_in[2];
    const float* Wq = (const float*)d_in[3];
    const float* bq = (const float*)d_in[4];
    const float* Wk = (const float*)d_in[5];
    const float* bk = (const float*)d_in[6];
    const float* Wv = (const float*)d_in[7];
    const float* bv = (const float*)d_in[8];
    const float* Wo = (const float*)d_in[9];
    const float* bo = (const float*)d_in[10];
    const float* scale = (const float*)d_in[11];
    float* out = (float*)d_out;

    void *p_qsig, *p_kp, *p_vp, *p_img;
    cudaGetSymbolAddress(&p_qsig, g_qsig);
    cudaGetSymbolAddress(&p_kp,   g_kp);
    cudaGetSymbolAddress(&p_vp,   g_vp);
    cudaGetSymbolAddress(&p_img,  g_img);

    const int attn_smem = ATTN_SMEM_FLOATS * (int)sizeof(float);
    cudaFuncSetAttribute(attn_kernel,
                         cudaFuncAttributeMaxDynamicSharedMemorySize, attn_smem);

    dim3 gdim((ROWS + 63) / 64, DM / 64, 1);   // (13, 8)
    // projections
    gemm_kernel<0><<<gdim, 256>>>(queries, Wq, bq, (float*)p_qsig, nullptr);
    gemm_kernel<0><<<gdim, 256>>>(keys,    Wk, bk, (float*)p_kp,   nullptr);
    gemm_kernel<0><<<gdim, 256>>>(values,  Wv, bv, (float*)p_vp,   nullptr);
    // fused attention core
    dim3 agrid((GRID_N + 7) / 8, NH, BB);      // (25, 8, 4)
    attn_kernel<<<agrid, 256, attn_smem>>>(scale);
    // output projection + gating
    gemm_kernel<1><<<gdim, 256>>>((const float*)p_img, Wo, bo, out,
                                  (const float*)p_qsig);
}

// round 4
// speedup vs baseline: 1.2776x; 1.2776x over previous
#include <cuda_runtime.h>
#include <math_constants.h>

#define BB 4
#define GRID_N 196
#define DM 512
#define NH 8
#define DK 64
#define ROWS (BB * GRID_N)   // 784

// ---- scratch (no allocations allowed) ----
__device__ float g_qsig[ROWS * DM];
__device__ float g_kp[ROWS * DM];
__device__ float g_vp[ROWS * DM];
__device__ float g_img[ROWS * DM];

__device__ __forceinline__ float sigm(float x) {
    return __fdividef(1.0f, 1.0f + __expf(-x));   // MUFU.EX2 + MUFU.RCP
}

// ============================================================
// GEMM tile body: out[r, j] = sum_c X[r, c] * W[j, c] + bias[j]
// EPILOGUE 0: plain; EPILOGUE 1: o=acc+b; out=o*sigmoid(qsig*o)
// Tile 64x64, K-chunk 16, 256 threads, 4x4 micro-tile.
// ============================================================
template <int EPILOGUE>
__device__ __forceinline__ void gemm_tile(const float* __restrict__ X,
                                          const float* __restrict__ W,
                                          const float* __restrict__ bias,
                                          float* __restrict__ out,
                                          const float* __restrict__ qsig) {
    __shared__ float As[16][68];
    __shared__ float Bs[16][68];

    const int t  = threadIdx.x;
    const int tx = t & 15;
    const int ty = t >> 4;
    const int r0 = blockIdx.x * 64;
    const int j0 = blockIdx.y * 64;

    const int lrow = t >> 2;
    const int c4   = (t & 3) << 2;

    float acc[4][4];
#pragma unroll
    for (int i = 0; i < 4; i++)
#pragma unroll
        for (int j = 0; j < 4; j++) acc[i][j] = 0.0f;

    for (int kc = 0; kc < DM; kc += 16) {
        float4 xv = make_float4(0.f, 0.f, 0.f, 0.f);
        const int gr = r0 + lrow;
        if (gr < ROWS) xv = *(const float4*)&X[gr * DM + kc + c4];
        const float4 wv = *(const float4*)&W[(j0 + lrow) * DM + kc + c4];
        As[c4 + 0][lrow] = xv.x; As[c4 + 1][lrow] = xv.y;
        As[c4 + 2][lrow] = xv.z; As[c4 + 3][lrow] = xv.w;
        Bs[c4 + 0][lrow] = wv.x; Bs[c4 + 1][lrow] = wv.y;
        Bs[c4 + 2][lrow] = wv.z; Bs[c4 + 3][lrow] = wv.w;
        __syncthreads();
#pragma unroll
        for (int kk = 0; kk < 16; kk++) {
            const float4 a = *(const float4*)&As[kk][ty << 2];
            const float4 b = *(const float4*)&Bs[kk][tx << 2];
            const float av[4] = {a.x, a.y, a.z, a.w};
            const float bv[4] = {b.x, b.y, b.z, b.w};
#pragma unroll
            for (int i = 0; i < 4; i++)
#pragma unroll
                for (int j = 0; j < 4; j++)
                    acc[i][j] = fmaf(av[i], bv[j], acc[i][j]);
        }
        __syncthreads();
    }

    const int jc = j0 + (tx << 2);
    const float4 bv4 = *(const float4*)&bias[jc];
#pragma unroll
    for (int i = 0; i < 4; i++) {
        const int r = r0 + (ty << 2) + i;
        if (r >= ROWS) continue;
        float4 o;
        o.x = acc[i][0] + bv4.x;
        o.y = acc[i][1] + bv4.y;
        o.z = acc[i][2] + bv4.z;
        o.w = acc[i][3] + bv4.w;
        if (EPILOGUE == 1) {
            const float4 q = *(const float4*)&qsig[r * DM + jc];
            o.x *= sigm(q.x * o.x);
            o.y *= sigm(q.y * o.y);
            o.z *= sigm(q.z * o.z);
            o.w *= sigm(q.w * o.w);
        }
        *(float4*)&out[r * DM + jc] = o;
    }
}

// All three projections in one launch: blockIdx.z selects {q,k,v}.
__global__ void __launch_bounds__(256)
proj3_kernel(const float* Xq, const float* Xk, const float* Xv,
             const float* Wq, const float* Wk, const float* Wv,
             const float* bq, const float* bk, const float* bv,
             float* Oq, float* Ok, float* Ov) {
    const float* X; const float* W; const float* B; float* O;
    if (blockIdx.z == 0)      { X = Xq; W = Wq; B = bq; O = Oq; }
    else if (blockIdx.z == 1) { X = Xk; W = Wk; B = bk; O = Ok; }
    else                      { X = Xv; W = Wv; B = bv; O = Ov; }
    gemm_tile<0>(X, W, B, O, nullptr);
}

__global__ void __launch_bounds__(256)
gemm_out_kernel(const float* __restrict__ X, const float* __restrict__ W,
                const float* __restrict__ bias, float* __restrict__ out,
                const float* __restrict__ qsig) {
    gemm_tile<1>(X, W, bias, out, qsig);
}

// ============================================================
// Fused attention core.
// block = (b, h, q-tile of 28); 896 threads; warp w handles one q.
// smem: K (196x64 @ stride 66), V (196x64 @ stride 64), q rows, p rows.
//   image[b,h,q,d] = sum_k p[q,k] * sigmoid(qs[q,d]*kp[k,d]) * vp[k,d]
// ============================================================
#define QT 28
#define KST 66
#define VST 64
#define ATTN_SMEM_FLOATS (GRID_N * KST + GRID_N * VST + QT * 64 + QT * 200)

__global__ void __launch_bounds__(QT * 32)
attn_kernel(const float* __restrict__ scale) {
    extern __shared__ float sm[];
    float* kp = sm;
    float* vp = kp + GRID_N * KST;
    float* qs = vp + GRID_N * VST;
    float* ps = qs + QT * 64;

    const int t  = threadIdx.x;
    const int q0 = blockIdx.x * QT;
    const int h  = blockIdx.y;
    const int b  = blockIdx.z;
    const int hbase = h * DK;

    // ---- load K,V head slices into smem ----
    for (int idx = t; idx < GRID_N * 16; idx += QT * 32) {
        const int s  = idx >> 4;
        const int d4 = (idx & 15) << 2;
        const int g  = (b * GRID_N + s) * DM + hbase + d4;
        const float4 kv = *(const float4*)&g_kp[g];
        const float4 vv = *(const float4*)&g_vp[g];
        float* kd = &kp[s * KST + d4];
        kd[0] = kv.x; kd[1] = kv.y; kd[2] = kv.z; kd[3] = kv.w;
        float* vd = &vp[s * VST + d4];
        vd[0] = vv.x; vd[1] = vv.y; vd[2] = vv.z; vd[3] = vv.w;
    }
    // ---- load q rows (196 = 7*28 exactly: all q valid) ----
    for (int idx = t; idx < QT * 64; idx += QT * 32) {
        const int w = idx >> 6;
        const int d = idx & 63;
        qs[idx] = g_qsig[(b * GRID_N + q0 + w) * DM + hbase + d];
    }
    __syncthreads();

    const int w    = t >> 5;
    const int lane = t & 31;
    const int q    = q0 + w;
    const float* qrow = &qs[w * 64];

    // ---- pass 1: att[k] = scale * <q_row, k_row> ; lanes over k ----
    const float* rp[7];
#pragma unroll
    for (int j = 0; j < 7; j++) {
        const int k = lane + 32 * j;
        rp[j] = &kp[(k < GRID_N ? k : GRID_N - 1) * KST];
    }
    float att[7];
#pragma unroll
    for (int j = 0; j < 7; j++) att[j] = 0.0f;

#pragma unroll 8
    for (int d = 0; d < 64; d += 2) {
        const float2 qd = *(const float2*)&qrow[d];
#pragma unroll
        for (int j = 0; j < 7; j++) {
            const float2 kv = *(const float2*)&rp[j][d];
            att[j] = fmaf(qd.x, kv.x, fmaf(qd.y, kv.y, att[j]));
        }
    }
    const float* srow = &scale[(h * GRID_N + q) * GRID_N];
#pragma unroll
    for (int j = 0; j < 7; j++) {
        const int k = lane + 32 * j;
        att[j] = (k < GRID_N) ? att[j] * srow[k] : -CUDART_INF_F;
    }

    // ---- warp softmax over 196 k ----
    float m = att[0];
#pragma unroll
    for (int j = 1; j < 7; j++) m = fmaxf(m, att[j]);
#pragma unroll
    for (int off = 16; off > 0; off >>= 1)
        m = fmaxf(m, __shfl_xor_sync(0xFFFFFFFFu, m, off));
    float ssum = 0.0f;
#pragma unroll
    for (int j = 0; j < 7; j++) {
        att[j] = __expf(att[j] - m);
        ssum += att[j];
    }
#pragma unroll
    for (int off = 16; off > 0; off >>= 1)
        ssum += __shfl_xor_sync(0xFFFFFFFFu, ssum, off);
    const float inv = __fdividef(1.0f, ssum);
    float* pw = &ps[w * 200];
#pragma unroll
    for (int j = 0; j < 7; j++) {
        const int k = lane + 32 * j;
        if (k < GRID_N) pw[k] = att[j] * inv;
    }
    __syncwarp();

    // ---- pass 2: sigmoid-gated PV ; lanes over d (2 per lane) ----
    const float nq0 = -qrow[2 * lane];
    const float nq1 = -qrow[2 * lane + 1];
    float accx = 0.0f, accy = 0.0f;
#pragma unroll 4
    for (int k = 0; k < GRID_N; k++) {
        const float  pk = pw[k];
        const float2 kv = *(const float2*)&kp[k * KST + 2 * lane];
        const float2 vv = *(const float2*)&vp[k * VST + 2 * lane];
        const float s0 = __fdividef(1.0f, 1.0f + __expf(nq0 * kv.x));
        const float s1 = __fdividef(1.0f, 1.0f + __expf(nq1 * kv.y));
        accx = fmaf(pk, s0 * vv.x, accx);
        accy = fmaf(pk, s1 * vv.y, accy);
    }
    float2 r;
    r.x = accx;
    r.y = accy;
    *(float2*)&g_img[(b * GRID_N + q) * DM + hbase + 2 * lane] = r;
}

// ============================================================
extern "C" void kernel_launch(void* const* d_in, const int* in_sizes, int n_in,
                              void* d_out, int out_size) {
    (void)in_sizes; (void)n_in; (void)out_size;
    const float* queries = (const float*)d_in[0];
    const float* keys    = (const float*)d_in[1];
    const float* values  = (const float*)d_in[2];
    const float* Wq = (const float*)d_in[3];
    const float* bq = (const float*)d_in[4];
    const float* Wk = (const float*)d_in[5];
    const float* bk = (const float*)d_in[6];
    const float* Wv = (const float*)d_in[7];
    const float* bv = (const float*)d_in[8];
    const float* Wo = (const float*)d_in[9];
    const float* bo = (const float*)d_in[10];
    const float* scale = (const float*)d_in[11];
    float* out = (float*)d_out;

    void *p_qsig, *p_kp, *p_vp, *p_img;
    cudaGetSymbolAddress(&p_qsig, g_qsig);
    cudaGetSymbolAddress(&p_kp,   g_kp);
    cudaGetSymbolAddress(&p_vp,   g_vp);
    cudaGetSymbolAddress(&p_img,  g_img);

    const int attn_smem = ATTN_SMEM_FLOATS * (int)sizeof(float);
    cudaFuncSetAttribute(attn_kernel,
                         cudaFuncAttributeMaxDynamicSharedMemorySize, attn_smem);

    dim3 pgrid((ROWS + 63) / 64, DM / 64, 3);  // (13, 8, 3) — all projections
    proj3_kernel<<<pgrid, 256>>>(queries, keys, values,
                                 Wq, Wk, Wv, bq, bk, bv,
                                 (float*)p_qsig, (float*)p_kp, (float*)p_vp);

    dim3 agrid(GRID_N / QT, NH, BB);           // (7, 8, 4)
    attn_kernel<<<agrid, QT * 32, attn_smem>>>(scale);

    dim3 ogrid((ROWS + 63) / 64, DM / 64, 1);  // (13, 8)
    gemm_out_kernel<<<ogrid, 256>>>((const float*)p_img, Wo, bo, out,
                                    (const float*)p_qsig);
}

// round 6
// speedup vs baseline: 1.4446x; 1.1307x over previous
#include <cuda_runtime.h>
#include <math_constants.h>

#define BB 4
#define GRID_N 196
#define DM 512
#define NH 8
#define DK 64
#define ROWS (BB * GRID_N)   // 784

// ---- scratch (no allocations allowed) ----
__device__ float g_qsig[ROWS * DM];
__device__ float g_kp[ROWS * DM];
__device__ float g_vp[ROWS * DM];
__device__ float g_img[ROWS * DM];

__device__ __forceinline__ float sigm_exact(float x) {
    return __fdividef(1.0f, 1.0f + __expf(-x));   // MUFU.EX2 + MUFU.RCP
}
__device__ __forceinline__ float sigm_fast(float x) {
    // sigmoid(x) = 0.5*tanh(x/2) + 0.5  -> single MUFU.TANH
    float t;
    asm("tanh.approx.f32 %0, %1;" : "=f"(t) : "f"(0.5f * x));
    return fmaf(0.5f, t, 0.5f);
}

// ============================================================
// GEMM tile body: out[r, j] = sum_c X[r, c] * W[j, c] + bias[j]
// EPILOGUE 0: plain; EPILOGUE 1: o=acc+b; out=o*sigmoid(qsig*o)
// Tile 64x64, K-chunk 16, 256 threads, 4x4 micro-tile,
// DOUBLE-BUFFERED smem: one __syncthreads per chunk, global
// loads for chunk c+1 issued before computing chunk c.
// ============================================================
#define NCHUNK (DM / 16)   // 32

template <int EPILOGUE>
__device__ __forceinline__ void gemm_tile(const float* __restrict__ X,
                                          const float* __restrict__ W,
                                          const float* __restrict__ bias,
                                          float* __restrict__ out,
                                          const float* __restrict__ qsig) {
    __shared__ float As[2][16][68];
    __shared__ float Bs[2][16][68];

    const int t  = threadIdx.x;
    const int tx = t & 15;
    const int ty = t >> 4;
    const int r0 = blockIdx.x * 64;
    const int j0 = blockIdx.y * 64;

    const int lrow = t >> 2;
    const int c4   = (t & 3) << 2;

    // clamp OOB rows (results discarded at write; avoids branchy zero-fill)
    const int gr = min(r0 + lrow, ROWS - 1);
    const float* Xp = &X[gr * DM + c4];
    const float* Wp = &W[(j0 + lrow) * DM + c4];

    float acc[4][4];
#pragma unroll
    for (int i = 0; i < 4; i++)
#pragma unroll
        for (int j = 0; j < 4; j++) acc[i][j] = 0.0f;

    // preload chunk 0 into buffer 0
    {
        const float4 xv = *(const float4*)Xp;
        const float4 wv = *(const float4*)Wp;
        As[0][c4 + 0][lrow] = xv.x; As[0][c4 + 1][lrow] = xv.y;
        As[0][c4 + 2][lrow] = xv.z; As[0][c4 + 3][lrow] = xv.w;
        Bs[0][c4 + 0][lrow] = wv.x; Bs[0][c4 + 1][lrow] = wv.y;
        Bs[0][c4 + 2][lrow] = wv.z; Bs[0][c4 + 3][lrow] = wv.w;
    }
    __syncthreads();

    int buf = 0;
#pragma unroll 1
    for (int c = 0; c < NCHUNK; c++) {
        float4 xn, wn;
        const bool more = (c + 1 < NCHUNK);
        if (more) {
            xn = *(const float4*)(Xp + (c + 1) * 16);
            wn = *(const float4*)(Wp + (c + 1) * 16);
        }
#pragma unroll
        for (int kk = 0; kk < 16; kk++) {
            const float4 a = *(const float4*)&As[buf][kk][ty << 2];
            const float4 b = *(const float4*)&Bs[buf][kk][tx << 2];
            const float av[4] = {a.x, a.y, a.z, a.w};
            const float bv[4] = {b.x, b.y, b.z, b.w};
#pragma unroll
            for (int i = 0; i < 4; i++)
#pragma unroll
                for (int j = 0; j < 4; j++)
                    acc[i][j] = fmaf(av[i], bv[j], acc[i][j]);
        }
        if (more) {
            const int nb = buf ^ 1;
            As[nb][c4 + 0][lrow] = xn.x; As[nb][c4 + 1][lrow] = xn.y;
            As[nb][c4 + 2][lrow] = xn.z; As[nb][c4 + 3][lrow] = xn.w;
            Bs[nb][c4 + 0][lrow] = wn.x; Bs[nb][c4 + 1][lrow] = wn.y;
            Bs[nb][c4 + 2][lrow] = wn.z; Bs[nb][c4 + 3][lrow] = wn.w;
            __syncthreads();
            buf = nb;
        }
    }

    const int jc = j0 + (tx << 2);
    const float4 bv4 = *(const float4*)&bias[jc];
#pragma unroll
    for (int i = 0; i < 4; i++) {
        const int r = r0 + (ty << 2) + i;
        if (r >= ROWS) continue;
        float4 o;
        o.x = acc[i][0] + bv4.x;
        o.y = acc[i][1] + bv4.y;
        o.z = acc[i][2] + bv4.z;
        o.w = acc[i][3] + bv4.w;
        if (EPILOGUE == 1) {
            const float4 q = *(const float4*)&qsig[r * DM + jc];
            o.x *= sigm_exact(q.x * o.x);
            o.y *= sigm_exact(q.y * o.y);
            o.z *= sigm_exact(q.z * o.z);
            o.w *= sigm_exact(q.w * o.w);
        }
        *(float4*)&out[r * DM + jc] = o;
    }
}

// All three projections in one launch: blockIdx.z selects {q,k,v}.
__global__ void __launch_bounds__(256)
proj3_kernel(const float* Xq, const float* Xk, const float* Xv,
             const float* Wq, const float* Wk, const float* Wv,
             const float* bq, const float* bk, const float* bv,
             float* Oq, float* Ok, float* Ov) {
    const float* X; const float* W; const float* B; float* O;
    if (blockIdx.z == 0)      { X = Xq; W = Wq; B = bq; O = Oq; }
    else if (blockIdx.z == 1) { X = Xk; W = Wk; B = bk; O = Ok; }
    else                      { X = Xv; W = Wv; B = bv; O = Ov; }
    gemm_tile<0>(X, W, B, O, nullptr);
}

__global__ void __launch_bounds__(256)
gemm_out_kernel(const float* __restrict__ X, const float* __restrict__ W,
                const float* __restrict__ bias, float* __restrict__ out,
                const float* __restrict__ qsig) {
    gemm_tile<1>(X, W, bias, out, qsig);
}

// ============================================================
// Fused attention core.
// block = (b, h, q-tile of 28); 896 threads; warp w handles one q.
// smem: K (196x64 @ stride 66), V (196x64 @ stride 64), q rows, p rows.
//   image[b,h,q,d] = sum_k p[q,k] * sigmoid(qs[q,d]*kp[k,d]) * vp[k,d]
// ============================================================
#define QT 28
#define KST 66
#define VST 64
#define ATTN_SMEM_FLOATS (GRID_N * KST + GRID_N * VST + QT * 64 + QT * 200)

__global__ void __launch_bounds__(QT * 32)
attn_kernel(const float* __restrict__ scale) {
    extern __shared__ float sm[];
    float* kp = sm;
    float* vp = kp + GRID_N * KST;
    float* qs = vp + GRID_N * VST;
    float* ps = qs + QT * 64;

    const int t  = threadIdx.x;
    const int q0 = blockIdx.x * QT;
    const int h  = blockIdx.y;
    const int b  = blockIdx.z;
    const int hbase = h * DK;

    // ---- load K,V head slices into smem ----
    for (int idx = t; idx < GRID_N * 16; idx += QT * 32) {
        const int s  = idx >> 4;
        const int d4 = (idx & 15) << 2;
        const int g  = (b * GRID_N + s) * DM + hbase + d4;
        const float4 kv = *(const float4*)&g_kp[g];
        const float4 vv = *(const float4*)&g_vp[g];
        float* kd = &kp[s * KST + d4];
        kd[0] = kv.x; kd[1] = kv.y; kd[2] = kv.z; kd[3] = kv.w;
        float* vd = &vp[s * VST + d4];
        vd[0] = vv.x; vd[1] = vv.y; vd[2] = vv.z; vd[3] = vv.w;
    }
    // ---- load q rows (196 = 7*28 exactly: all q valid) ----
    for (int idx = t; idx < QT * 64; idx += QT * 32) {
        const int w = idx >> 6;
        const int d = idx & 63;
        qs[idx] = g_qsig[(b * GRID_N + q0 + w) * DM + hbase + d];
    }
    __syncthreads();

    const int w    = t >> 5;
    const int lane = t & 31;
    const int q    = q0 + w;
    const float* qrow = &qs[w * 64];

    // ---- pass 1: att[k] = scale * <q_row, k_row> ; lanes over k ----
    const float* rp[7];
#pragma unroll
    for (int j = 0; j < 7; j++) {
        const int k = lane + 32 * j;
        rp[j] = &kp[(k < GRID_N ? k : GRID_N - 1) * KST];
    }
    float att[7];
#pragma unroll
    for (int j = 0; j < 7; j++) att[j] = 0.0f;

#pragma unroll 8
    for (int d = 0; d < 64; d += 2) {
        const float2 qd = *(const float2*)&qrow[d];
#pragma unroll
        for (int j = 0; j < 7; j++) {
            const float2 kv = *(const float2*)&rp[j][d];
            att[j] = fmaf(qd.x, kv.x, fmaf(qd.y, kv.y, att[j]));
        }
    }
    const float* srow = &scale[(h * GRID_N + q) * GRID_N];
#pragma unroll
    for (int j = 0; j < 7; j++) {
        const int k = lane + 32 * j;
        att[j] = (k < GRID_N) ? att[j] * srow[k] : -CUDART_INF_F;
    }

    // ---- warp softmax over 196 k ----
    float m = att[0];
#pragma unroll
    for (int j = 1; j < 7; j++) m = fmaxf(m, att[j]);
#pragma unroll
    for (int off = 16; off > 0; off >>= 1)
        m = fmaxf(m, __shfl_xor_sync(0xFFFFFFFFu, m, off));
    float ssum = 0.0f;
#pragma unroll
    for (int j = 0; j < 7; j++) {
        att[j] = __expf(att[j] - m);
        ssum += att[j];
    }
#pragma unroll
    for (int off = 16; off > 0; off >>= 1)
        ssum += __shfl_xor_sync(0xFFFFFFFFu, ssum, off);
    const float inv = __fdividef(1.0f, ssum);
    float* pw = &ps[w * 200];
#pragma unroll
    for (int j = 0; j < 7; j++) {
        const int k = lane + 32 * j;
        if (k < GRID_N) pw[k] = att[j] * inv;
    }
    __syncwarp();

    // ---- pass 2: sigmoid-gated PV ; lanes over d (2 per lane) ----
    const float q0v = qrow[2 * lane];
    const float q1v = qrow[2 * lane + 1];
    float accx = 0.0f, accy = 0.0f;
#pragma unroll 4
    for (int k = 0; k < GRID_N; k++) {
        const float  pk = pw[k];
        const float2 kv = *(const float2*)&kp[k * KST + 2 * lane];
        const float2 vv = *(const float2*)&vp[k * VST + 2 * lane];
        const float s0 = sigm_fast(q0v * kv.x);
        const float s1 = sigm_fast(q1v * kv.y);
        accx = fmaf(pk, s0 * vv.x, accx);
        accy = fmaf(pk, s1 * vv.y, accy);
    }
    float2 r;
    r.x = accx;
    r.y = accy;
    *(float2*)&g_img[(b * GRID_N + q) * DM + hbase + 2 * lane] = r;
}

// ============================================================
extern "C" void kernel_launch(void* const* d_in, const int* in_sizes, int n_in,
                              void* d_out, int out_size) {
    (void)in_sizes; (void)n_in; (void)out_size;
    const float* queries = (const float*)d_in[0];
    const float* keys    = (const float*)d_in[1];
    const float* values  = (const float*)d_in[2];
    const float* Wq = (const float*)d_in[3];
    const float* bq = (const float*)d_in[4];
    const float* Wk = (const float*)d_in[5];
    const float* bk = (const float*)d_in[6];
    const float* Wv = (const float*)d_in[7];
    const float* bv = (const float*)d_in[8];
    const float* Wo = (const float*)d_in[9];
    const float* bo = (const float*)d_in[10];
    const float* scale = (const float*)d_in[11];
    float* out = (float*)d_out;

    void *p_qsig, *p_kp, *p_vp, *p_img;
    cudaGetSymbolAddress(&p_qsig, g_qsig);
    cudaGetSymbolAddress(&p_kp,   g_kp);
    cudaGetSymbolAddress(&p_vp,   g_vp);
    cudaGetSymbolAddress(&p_img,  g_img);

    const int attn_smem = ATTN_SMEM_FLOATS * (int)sizeof(float);
    cudaFuncSetAttribute(attn_kernel,
                         cudaFuncAttributeMaxDynamicSharedMemorySize, attn_smem);

    dim3 pgrid((ROWS + 63) / 64, DM / 64, 3);  // (13, 8, 3) — all projections
    proj3_kernel<<<pgrid, 256>>>(queries, keys, values,
                                 Wq, Wk, Wv, bq, bk, bv,
                                 (float*)p_qsig, (float*)p_kp, (float*)p_vp);

    dim3 agrid(GRID_N / QT, NH, BB);           // (7, 8, 4)
    attn_kernel<<<agrid, QT * 32, attn_smem>>>(scale);

    dim3 ogrid((ROWS + 63) / 64, DM / 64, 1);  // (13, 8)
    gemm_out_kernel<<<ogrid, 256>>>((const float*)p_img, Wo, bo, out,
                                    (const float*)p_qsig);
}

// round 8
// speedup vs baseline: 1.5632x; 1.0821x over previous
#include <cuda_runtime.h>
#include <math_constants.h>

#define BB 4
#define GRID_N 196
#define DM 512
#define NH 8
#define DK 64
#define ROWS (BB * GRID_N)   // 784

// ---- scratch (no allocations allowed) ----
__device__ float g_qsig[ROWS * DM];
__device__ float g_kp[ROWS * DM];
__device__ float g_vp[ROWS * DM];
__device__ float g_img[ROWS * DM];

__device__ __forceinline__ float sigm_exact(float x) {
    return __fdividef(1.0f, 1.0f + __expf(-x));
}
__device__ __forceinline__ float sigm_fast(float x) {
    float t;
    asm("tanh.approx.f32 %0, %1;" : "=f"(t) : "f"(0.5f * x));
    return fmaf(0.5f, t, 0.5f);
}

// ============================================================
// GEMM: out[r, j] = sum_c X[r, c] * W[j, c] + bias[j]
// Tile 64x64, K-chunk 32, 256 threads, 4x4 micro-tile,
// double-buffered smem (one sync per 32-deep chunk).
// ============================================================
#define KC 32
#define NCHUNK (DM / KC)   // 16

template <int EPILOGUE>
__device__ __forceinline__ void gemm_tile(const float* __restrict__ X,
                                          const float* __restrict__ W,
                                          const float* __restrict__ bias,
                                          float* __restrict__ out,
                                          const float* __restrict__ qsig) {
    __shared__ float As[2][KC][68];
    __shared__ float Bs[2][KC][68];

    const int t  = threadIdx.x;
    const int tx = t & 15;
    const int ty = t >> 4;
    const int r0 = blockIdx.x * 64;
    const int j0 = blockIdx.y * 64;

    const int lrow = t >> 2;        // 0..63
    const int c4   = (t & 3) << 2;  // 0,4,8,12

    const int gr = min(r0 + lrow, ROWS - 1);
    const float* Xp = &X[gr * DM + c4];
    const float* Wp = &W[(j0 + lrow) * DM + c4];

    float acc[4][4];
#pragma unroll
    for (int i = 0; i < 4; i++)
#pragma unroll
        for (int j = 0; j < 4; j++) acc[i][j] = 0.0f;

    // preload chunk 0 -> buffer 0
    {
        const float4 x0 = *(const float4*)(Xp);
        const float4 x1 = *(const float4*)(Xp + 16);
        const float4 w0 = *(const float4*)(Wp);
        const float4 w1 = *(const float4*)(Wp + 16);
        As[0][c4 + 0][lrow] = x0.x; As[0][c4 + 1][lrow] = x0.y;
        As[0][c4 + 2][lrow] = x0.z; As[0][c4 + 3][lrow] = x0.w;
        As[0][c4 + 16][lrow] = x1.x; As[0][c4 + 17][lrow] = x1.y;
        As[0][c4 + 18][lrow] = x1.z; As[0][c4 + 19][lrow] = x1.w;
        Bs[0][c4 + 0][lrow] = w0.x; Bs[0][c4 + 1][lrow] = w0.y;
        Bs[0][c4 + 2][lrow] = w0.z; Bs[0][c4 + 3][lrow] = w0.w;
        Bs[0][c4 + 16][lrow] = w1.x; Bs[0][c4 + 17][lrow] = w1.y;
        Bs[0][c4 + 18][lrow] = w1.z; Bs[0][c4 + 19][lrow] = w1.w;
    }
    __syncthreads();

    int buf = 0;
#pragma unroll 1
    for (int c = 0; c < NCHUNK; c++) {
        float4 x0, x1, w0, w1;
        const bool more = (c + 1 < NCHUNK);
        if (more) {
            const float* xp = Xp + (c + 1) * KC;
            const float* wp = Wp + (c + 1) * KC;
            x0 = *(const float4*)(xp);
            x1 = *(const float4*)(xp + 16);
            w0 = *(const float4*)(wp);
            w1 = *(const float4*)(wp + 16);
        }
#pragma unroll
        for (int kk = 0; kk < KC; kk++) {
            const float4 a = *(const float4*)&As[buf][kk][ty << 2];
            const float4 b = *(const float4*)&Bs[buf][kk][tx << 2];
            const float av[4] = {a.x, a.y, a.z, a.w};
            const float bv[4] = {b.x, b.y, b.z, b.w};
#pragma unroll
            for (int i = 0; i < 4; i++)
#pragma unroll
                for (int j = 0; j < 4; j++)
                    acc[i][j] = fmaf(av[i], bv[j], acc[i][j]);
        }
        if (more) {
            const int nb = buf ^ 1;
            As[nb][c4 + 0][lrow] = x0.x; As[nb][c4 + 1][lrow] = x0.y;
            As[nb][c4 + 2][lrow] = x0.z; As[nb][c4 + 3][lrow] = x0.w;
            As[nb][c4 + 16][lrow] = x1.x; As[nb][c4 + 17][lrow] = x1.y;
            As[nb][c4 + 18][lrow] = x1.z; As[nb][c4 + 19][lrow] = x1.w;
            Bs[nb][c4 + 0][lrow] = w0.x; Bs[nb][c4 + 1][lrow] = w0.y;
            Bs[nb][c4 + 2][lrow] = w0.z; Bs[nb][c4 + 3][lrow] = w0.w;
            Bs[nb][c4 + 16][lrow] = w1.x; Bs[nb][c4 + 17][lrow] = w1.y;
            Bs[nb][c4 + 18][lrow] = w1.z; Bs[nb][c4 + 19][lrow] = w1.w;
            __syncthreads();
            buf = nb;
        }
    }

    const int jc = j0 + (tx << 2);
    const float4 bv4 = *(const float4*)&bias[jc];
#pragma unroll
    for (int i = 0; i < 4; i++) {
        const int r = r0 + (ty << 2) + i;
        if (r >= ROWS) continue;
        float4 o;
        o.x = acc[i][0] + bv4.x;
        o.y = acc[i][1] + bv4.y;
        o.z = acc[i][2] + bv4.z;
        o.w = acc[i][3] + bv4.w;
        if (EPILOGUE == 1) {
            const float4 q = *(const float4*)&qsig[r * DM + jc];
            o.x *= sigm_exact(q.x * o.x);
            o.y *= sigm_exact(q.y * o.y);
            o.z *= sigm_exact(q.z * o.z);
            o.w *= sigm_exact(q.w * o.w);
        }
        *(float4*)&out[r * DM + jc] = o;
    }
}

__global__ void __launch_bounds__(256, 2)
proj3_kernel(const float* Xq, const float* Xk, const float* Xv,
             const float* Wq, const float* Wk, const float* Wv,
             const float* bq, const float* bk, const float* bv,
             float* Oq, float* Ok, float* Ov) {
    const float* X; const float* W; const float* B; float* O;
    if (blockIdx.z == 0)      { X = Xq; W = Wq; B = bq; O = Oq; }
    else if (blockIdx.z == 1) { X = Xk; W = Wk; B = bk; O = Ok; }
    else                      { X = Xv; W = Wv; B = bv; O = Ov; }
    gemm_tile<0>(X, W, B, O, nullptr);
}

__global__ void __launch_bounds__(256, 2)
gemm_out_kernel(const float* __restrict__ X, const float* __restrict__ W,
                const float* __restrict__ bias, float* __restrict__ out,
                const float* __restrict__ qsig) {
    gemm_tile<1>(X, W, bias, out, qsig);
}

// ============================================================
// Fused attention core — 2 queries per warp (amortizes K/V smem reads).
// block = (b, h, q-tile of 28); 14 warps (448 thr); warp w -> q0+2w, q0+2w+1.
// ============================================================
#define QT 28
#define NW 14
#define NT (NW * 32)
#define KST 66
#define VST 64
#define ATTN_SMEM_FLOATS (GRID_N * KST + GRID_N * VST + QT * 64 + QT * 200)

__global__ void __launch_bounds__(NT)
attn_kernel(const float* __restrict__ scale) {
    extern __shared__ float sm[];
    float* kp = sm;
    float* vp = kp + GRID_N * KST;
    float* qs = vp + GRID_N * VST;
    float* ps = qs + QT * 64;

    const int t  = threadIdx.x;
    const int q0 = blockIdx.x * QT;
    const int h  = blockIdx.y;
    const int b  = blockIdx.z;
    const int hbase = h * DK;

    // ---- load K,V head slices ----
    for (int idx = t; idx < GRID_N * 16; idx += NT) {
        const int s  = idx >> 4;
        const int d4 = (idx & 15) << 2;
        const int g  = (b * GRID_N + s) * DM + hbase + d4;
        const float4 kv = *(const float4*)&g_kp[g];
        const float4 vv = *(const float4*)&g_vp[g];
        float* kd = &kp[s * KST + d4];
        kd[0] = kv.x; kd[1] = kv.y; kd[2] = kv.z; kd[3] = kv.w;
        float* vd = &vp[s * VST + d4];
        vd[0] = vv.x; vd[1] = vv.y; vd[2] = vv.z; vd[3] = vv.w;
    }
    // ---- load q rows ----
    for (int idx = t; idx < QT * 64; idx += NT) {
        const int w = idx >> 6;
        const int d = idx & 63;
        qs[idx] = g_qsig[(b * GRID_N + q0 + w) * DM + hbase + d];
    }
    __syncthreads();

    const int w    = t >> 5;
    const int lane = t & 31;
    const int qA   = q0 + 2 * w;
    const int qB   = qA + 1;
    const float* qrowA = &qs[(2 * w) * 64];
    const float* qrowB = qrowA + 64;

    // ---- pass 1: two dot-product rows, K reads shared ----
    const float* rp[7];
#pragma unroll
    for (int j = 0; j < 7; j++) {
        const int k = lane + 32 * j;
        rp[j] = &kp[(k < GRID_N ? k : GRID_N - 1) * KST];
    }
    float attA[7], attB[7];
#pragma unroll
    for (int j = 0; j < 7; j++) { attA[j] = 0.0f; attB[j] = 0.0f; }

#pragma unroll 8
    for (int d = 0; d < 64; d += 2) {
        const float2 qa = *(const float2*)&qrowA[d];
        const float2 qb = *(const float2*)&qrowB[d];
#pragma unroll
        for (int j = 0; j < 7; j++) {
            const float2 kv = *(const float2*)&rp[j][d];
            attA[j] = fmaf(qa.x, kv.x, fmaf(qa.y, kv.y, attA[j]));
            attB[j] = fmaf(qb.x, kv.x, fmaf(qb.y, kv.y, attB[j]));
        }
    }
    const float* srowA = &scale[(h * GRID_N + qA) * GRID_N];
    const float* srowB = &scale[(h * GRID_N + qB) * GRID_N];
#pragma unroll
    for (int j = 0; j < 7; j++) {
        const int k = lane + 32 * j;
        if (k < GRID_N) {
            attA[j] *= srowA[k];
            attB[j] *= srowB[k];
        } else {
            attA[j] = -CUDART_INF_F;
            attB[j] = -CUDART_INF_F;
        }
    }

    // ---- warp softmax (both rows) ----
    float mA = attA[0], mB = attB[0];
#pragma unroll
    for (int j = 1; j < 7; j++) { mA = fmaxf(mA, attA[j]); mB = fmaxf(mB, attB[j]); }
#pragma unroll
    for (int off = 16; off > 0; off >>= 1) {
        mA = fmaxf(mA, __shfl_xor_sync(0xFFFFFFFFu, mA, off));
        mB = fmaxf(mB, __shfl_xor_sync(0xFFFFFFFFu, mB, off));
    }
    float sA = 0.0f, sB = 0.0f;
#pragma unroll
    for (int j = 0; j < 7; j++) {
        attA[j] = __expf(attA[j] - mA); sA += attA[j];
        attB[j] = __expf(attB[j] - mB); sB += attB[j];
    }
#pragma unroll
    for (int off = 16; off > 0; off >>= 1) {
        sA += __shfl_xor_sync(0xFFFFFFFFu, sA, off);
        sB += __shfl_xor_sync(0xFFFFFFFFu, sB, off);
    }
    const float invA = __fdividef(1.0f, sA);
    const float invB = __fdividef(1.0f, sB);
    float* pwA = &ps[(2 * w) * 200];
    float* pwB = pwA + 200;
#pragma unroll
    for (int j = 0; j < 7; j++) {
        const int k = lane + 32 * j;
        if (k < GRID_N) {
            pwA[k] = attA[j] * invA;
            pwB[k] = attB[j] * invB;
        }
    }
    __syncwarp();

    // ---- pass 2: sigmoid-gated PV, K/V reads shared by both queries ----
    const float qA0 = qrowA[2 * lane], qA1 = qrowA[2 * lane + 1];
    const float qB0 = qrowB[2 * lane], qB1 = qrowB[2 * lane + 1];
    float aAx = 0.f, aAy = 0.f, aBx = 0.f, aBy = 0.f;
#pragma unroll 4
    for (int k = 0; k < GRID_N; k++) {
        const float  pA = pwA[k];
        const float  pB = pwB[k];
        const float2 kv = *(const float2*)&kp[k * KST + 2 * lane];
        const float2 vv = *(const float2*)&vp[k * VST + 2 * lane];
        const float sA0 = sigm_fast(qA0 * kv.x);
        const float sA1 = sigm_fast(qA1 * kv.y);
        const float sB0 = sigm_fast(qB0 * kv.x);
        const float sB1 = sigm_fast(qB1 * kv.y);
        aAx = fmaf(pA, sA0 * vv.x, aAx);
        aAy = fmaf(pA, sA1 * vv.y, aAy);
        aBx = fmaf(pB, sB0 * vv.x, aBx);
        aBy = fmaf(pB, sB1 * vv.y, aBy);
    }
    float2 rA; rA.x = aAx; rA.y = aAy;
    float2 rB; rB.x = aBx; rB.y = aBy;
    *(float2*)&g_img[(b * GRID_N + qA) * DM + hbase + 2 * lane] = rA;
    *(float2*)&g_img[(b * GRID_N + qB) * DM + hbase + 2 * lane] = rB;
}

// ============================================================
extern "C" void kernel_launch(void* const* d_in, const int* in_sizes, int n_in,
                              void* d_out, int out_size) {
    (void)in_sizes; (void)n_in; (void)out_size;
    const float* queries = (const float*)d_in[0];
    const float* keys    = (const float*)d_in[1];
    const float* values  = (const float*)d_in[2];
    const float* Wq = (const float*)d_in[3];
    const float* bq = (const float*)d_in[4];
    const float* Wk = (const float*)d_in[5];
    const float* bk = (const float*)d_in[6];
    const float* Wv = (const float*)d_in[7];
    const float* bv = (const float*)d_in[8];
    const float* Wo = (const float*)d_in[9];
    const float* bo = (const float*)d_in[10];
    const float* scale = (const float*)d_in[11];
    float* out = (float*)d_out;

    void *p_qsig, *p_kp, *p_vp, *p_img;
    cudaGetSymbolAddress(&p_qsig, g_qsig);
    cudaGetSymbolAddress(&p_kp,   g_kp);
    cudaGetSymbolAddress(&p_vp,   g_vp);
    cudaGetSymbolAddress(&p_img,  g_img);

    const int attn_smem = ATTN_SMEM_FLOATS * (int)sizeof(float);
    cudaFuncSetAttribute(attn_kernel,
                         cudaFuncAttributeMaxDynamicSharedMemorySize, attn_smem);

    dim3 pgrid((ROWS + 63) / 64, DM / 64, 3);  // (13, 8, 3)
    proj3_kernel<<<pgrid, 256>>>(queries, keys, values,
                                 Wq, Wk, Wv, bq, bk, bv,
                                 (float*)p_qsig, (float*)p_kp, (float*)p_vp);

    dim3 agrid(GRID_N / QT, NH, BB);           // (7, 8, 4)
    attn_kernel<<<agrid, NT, attn_smem>>>(scale);

    dim3 ogrid((ROWS + 63) / 64, DM / 64, 1);  // (13, 8)
    gemm_out_kernel<<<ogrid, 256>>>((const float*)p_img, Wo, bo, out,
                                    (const float*)p_qsig);
}

// round 9
// speedup vs baseline: 1.7601x; 1.1260x over previous
#include <cuda_runtime.h>
#include <math_constants.h>

#define BB 4
#define GRID_N 196
#define DM 512
#define NH 8
#define DK 64
#define ROWS (BB * GRID_N)   // 784

// ---- scratch (no allocations allowed) ----
__device__ float g_qsig[ROWS * DM];
__device__ float g_kp[ROWS * DM];
__device__ float g_vp[ROWS * DM];
__device__ float g_img[ROWS * DM];

__device__ __forceinline__ float sigm_exact(float x) {
    return __fdividef(1.0f, 1.0f + __expf(-x));
}
__device__ __forceinline__ float sigm_fast(float x) {
    float t;
    asm("tanh.approx.f32 %0, %1;" : "=f"(t) : "f"(0.5f * x));
    return fmaf(0.5f, t, 0.5f);
}

// ============================================================
// GEMM: out[r, j] = sum_c X[r, c] * W[j, c] + bias[j]
// Tile TM x TN, 4x4 micro-tile, T = TM*TN/16 threads,
// KC=32 double-buffered smem, XOR-swizzled stores
// (conflict-free STS.32, aligned LDS.128 reads).
// ============================================================
#define KC 32
#define NCHUNK (DM / KC)   // 16

template <int TM, int TN, int EPILOGUE>
__device__ __forceinline__ void gemm_tile(const float* __restrict__ X,
                                          const float* __restrict__ W,
                                          const float* __restrict__ bias,
                                          float* __restrict__ out,
                                          const float* __restrict__ qsig) {
    constexpr int T   = TM * TN / 16;   // threads
    constexpr int XL  = TM * 8 / T;     // float4 X loads/thread/chunk
    constexpr int WL  = TN * 8 / T;     // float4 W loads/thread/chunk
    constexpr int AST = TM + 4;
    constexpr int BST = TN + 4;

    __shared__ float As[2][KC][AST];
    __shared__ float Bs[2][KC][BST];

    const int t  = threadIdx.x;
    const int tx = t % (TN / 4);
    const int ty = t / (TN / 4);
    const int r0 = blockIdx.x * TM;
    const int j0 = blockIdx.y * TN;

    // loader lane geometry (row, 4-col group, swizzled row index)
    const float* xp[XL]; int xc4[XL], xrw[XL];
#pragma unroll
    for (int i = 0; i < XL; i++) {
        const int e   = t + i * T;
        const int row = e >> 3;
        const int c4  = (e & 7) << 2;
        xc4[i] = c4;
        xrw[i] = row ^ (((c4 >> 2) & 7) << 2);
        xp[i]  = &X[min(r0 + row, ROWS - 1) * DM + c4];
    }
    const float* wp[WL]; int wc4[WL], wrw[WL];
#pragma unroll
    for (int i = 0; i < WL; i++) {
        const int e   = t + i * T;
        const int row = e >> 3;
        const int c4  = (e & 7) << 2;
        wc4[i] = c4;
        wrw[i] = row ^ (((c4 >> 2) & 7) << 2);
        wp[i]  = &W[(j0 + row) * DM + c4];
    }

    float acc[4][4];
#pragma unroll
    for (int i = 0; i < 4; i++)
#pragma unroll
        for (int j = 0; j < 4; j++) acc[i][j] = 0.0f;

    // preload chunk 0 -> buffer 0
#pragma unroll
    for (int i = 0; i < XL; i++) {
        const float4 v = *(const float4*)xp[i];
        As[0][xc4[i] + 0][xrw[i]] = v.x;
        As[0][xc4[i] + 1][xrw[i]] = v.y;
        As[0][xc4[i] + 2][xrw[i]] = v.z;
        As[0][xc4[i] + 3][xrw[i]] = v.w;
    }
#pragma unroll
    for (int i = 0; i < WL; i++) {
        const float4 v = *(const float4*)wp[i];
        Bs[0][wc4[i] + 0][wrw[i]] = v.x;
        Bs[0][wc4[i] + 1][wrw[i]] = v.y;
        Bs[0][wc4[i] + 2][wrw[i]] = v.z;
        Bs[0][wc4[i] + 3][wrw[i]] = v.w;
    }
    __syncthreads();

    int buf = 0;
#pragma unroll 1
    for (int c = 0; c < NCHUNK; c++) {
        float4 xr[XL], wr[WL];
        const bool more = (c + 1 < NCHUNK);
        if (more) {
#pragma unroll
            for (int i = 0; i < XL; i++) xr[i] = *(const float4*)(xp[i] + (c + 1) * KC);
#pragma unroll
            for (int i = 0; i < WL; i++) wr[i] = *(const float4*)(wp[i] + (c + 1) * KC);
        }
#pragma unroll
        for (int kk = 0; kk < KC; kk++) {
            const int sw = ((kk >> 2) & 7) << 2;   // compile-time in unrolled loop
            const float4 a = *(const float4*)&As[buf][kk][(ty << 2) ^ sw];
            const float4 b = *(const float4*)&Bs[buf][kk][(tx << 2) ^ sw];
            const float av[4] = {a.x, a.y, a.z, a.w};
            const float bv[4] = {b.x, b.y, b.z, b.w};
#pragma unroll
            for (int i = 0; i < 4; i++)
#pragma unroll
                for (int j = 0; j < 4; j++)
                    acc[i][j] = fmaf(av[i], bv[j], acc[i][j]);
        }
        if (more) {
            const int nb = buf ^ 1;
#pragma unroll
            for (int i = 0; i < XL; i++) {
                As[nb][xc4[i] + 0][xrw[i]] = xr[i].x;
                As[nb][xc4[i] + 1][xrw[i]] = xr[i].y;
                As[nb][xc4[i] + 2][xrw[i]] = xr[i].z;
                As[nb][xc4[i] + 3][xrw[i]] = xr[i].w;
            }
#pragma unroll
            for (int i = 0; i < WL; i++) {
                Bs[nb][wc4[i] + 0][wrw[i]] = wr[i].x;
                Bs[nb][wc4[i] + 1][wrw[i]] = wr[i].y;
                Bs[nb][wc4[i] + 2][wrw[i]] = wr[i].z;
                Bs[nb][wc4[i] + 3][wrw[i]] = wr[i].w;
            }
            __syncthreads();
            buf = nb;
        }
    }

    const int jc = j0 + (tx << 2);
    const float4 bv4 = *(const float4*)&bias[jc];
#pragma unroll
    for (int i = 0; i < 4; i++) {
        const int r = r0 + (ty << 2) + i;
        if (r >= ROWS) continue;
        float4 o;
        o.x = acc[i][0] + bv4.x;
        o.y = acc[i][1] + bv4.y;
        o.z = acc[i][2] + bv4.z;
        o.w = acc[i][3] + bv4.w;
        if (EPILOGUE == 1) {
            const float4 q = *(const float4*)&qsig[r * DM + jc];
            o.x *= sigm_exact(q.x * o.x);
            o.y *= sigm_exact(q.y * o.y);
            o.z *= sigm_exact(q.z * o.z);
            o.w *= sigm_exact(q.w * o.w);
        }
        *(float4*)&out[r * DM + jc] = o;
    }
}

#define GTM 32
#define GTN 64
#define GTHREADS (GTM * GTN / 16)   // 128

__global__ void __launch_bounds__(GTHREADS, 4)
proj3_kernel(const float* Xq, const float* Xk, const float* Xv,
             const float* Wq, const float* Wk, const float* Wv,
             const float* bq, const float* bk, const float* bv,
             float* Oq, float* Ok, float* Ov) {
    const float* X; const float* W; const float* B; float* O;
    if (blockIdx.z == 0)      { X = Xq; W = Wq; B = bq; O = Oq; }
    else if (blockIdx.z == 1) { X = Xk; W = Wk; B = bk; O = Ok; }
    else                      { X = Xv; W = Wv; B = bv; O = Ov; }
    gemm_tile<GTM, GTN, 0>(X, W, B, O, nullptr);
}

__global__ void __launch_bounds__(GTHREADS, 4)
gemm_out_kernel(const float* __restrict__ X, const float* __restrict__ W,
                const float* __restrict__ bias, float* __restrict__ out,
                const float* __restrict__ qsig) {
    gemm_tile<GTM, GTN, 1>(X, W, bias, out, qsig);
}

// ============================================================
// Fused attention core — 2 queries per warp, q-tile 14 (7 warps)
// for finer wave granularity (448 CTAs, ~3/SM, dynamic packing).
// ============================================================
#define QT 14
#define NW 7
#define NT (NW * 32)
#define KST 66
#define VST 64
#define ATTN_SMEM_FLOATS (GRID_N * KST + GRID_N * VST + QT * 64 + QT * 200)

__global__ void __launch_bounds__(NT)
attn_kernel(const float* __restrict__ scale) {
    extern __shared__ float sm[];
    float* kp = sm;
    float* vp = kp + GRID_N * KST;
    float* qs = vp + GRID_N * VST;
    float* ps = qs + QT * 64;

    const int t  = threadIdx.x;
    const int q0 = blockIdx.x * QT;
    const int h  = blockIdx.y;
    const int b  = blockIdx.z;
    const int hbase = h * DK;

    // ---- load K,V head slices ----
    for (int idx = t; idx < GRID_N * 16; idx += NT) {
        const int s  = idx >> 4;
        const int d4 = (idx & 15) << 2;
        const int g  = (b * GRID_N + s) * DM + hbase + d4;
        const float4 kv = *(const float4*)&g_kp[g];
        const float4 vv = *(const float4*)&g_vp[g];
        float* kd = &kp[s * KST + d4];
        kd[0] = kv.x; kd[1] = kv.y; kd[2] = kv.z; kd[3] = kv.w;
        float* vd = &vp[s * VST + d4];
        vd[0] = vv.x; vd[1] = vv.y; vd[2] = vv.z; vd[3] = vv.w;
    }
    // ---- load q rows ----
    for (int idx = t; idx < QT * 64; idx += NT) {
        const int w = idx >> 6;
        const int d = idx & 63;
        qs[idx] = g_qsig[(b * GRID_N + q0 + w) * DM + hbase + d];
    }
    __syncthreads();

    const int w    = t >> 5;
    const int lane = t & 31;
    const int qA   = q0 + 2 * w;
    const int qB   = qA + 1;
    const float* qrowA = &qs[(2 * w) * 64];
    const float* qrowB = qrowA + 64;

    // ---- pass 1: two dot-product rows, K reads shared ----
    const float* rp[7];
#pragma unroll
    for (int j = 0; j < 7; j++) {
        const int k = lane + 32 * j;
        rp[j] = &kp[(k < GRID_N ? k : GRID_N - 1) * KST];
    }
    float attA[7], attB[7];
#pragma unroll
    for (int j = 0; j < 7; j++) { attA[j] = 0.0f; attB[j] = 0.0f; }

#pragma unroll 8
    for (int d = 0; d < 64; d += 2) {
        const float2 qa = *(const float2*)&qrowA[d];
        const float2 qb = *(const float2*)&qrowB[d];
#pragma unroll
        for (int j = 0; j < 7; j++) {
            const float2 kv = *(const float2*)&rp[j][d];
            attA[j] = fmaf(qa.x, kv.x, fmaf(qa.y, kv.y, attA[j]));
            attB[j] = fmaf(qb.x, kv.x, fmaf(qb.y, kv.y, attB[j]));
        }
    }
    const float* srowA = &scale[(h * GRID_N + qA) * GRID_N];
    const float* srowB = &scale[(h * GRID_N + qB) * GRID_N];
#pragma unroll
    for (int j = 0; j < 7; j++) {
        const int k = lane + 32 * j;
        if (k < GRID_N) {
            attA[j] *= srowA[k];
            attB[j] *= srowB[k];
        } else {
            attA[j] = -CUDART_INF_F;
            attB[j] = -CUDART_INF_F;
        }
    }

    // ---- warp softmax (both rows) ----
    float mA = attA[0], mB = attB[0];
#pragma unroll
    for (int j = 1; j < 7; j++) { mA = fmaxf(mA, attA[j]); mB = fmaxf(mB, attB[j]); }
#pragma unroll
    for (int off = 16; off > 0; off >>= 1) {
        mA = fmaxf(mA, __shfl_xor_sync(0xFFFFFFFFu, mA, off));
        mB = fmaxf(mB, __shfl_xor_sync(0xFFFFFFFFu, mB, off));
    }
    float sA = 0.0f, sB = 0.0f;
#pragma unroll
    for (int j = 0; j < 7; j++) {
        attA[j] = __expf(attA[j] - mA); sA += attA[j];
        attB[j] = __expf(attB[j] - mB); sB += attB[j];
    }
#pragma unroll
    for (int off = 16; off > 0; off >>= 1) {
        sA += __shfl_xor_sync(0xFFFFFFFFu, sA, off);
        sB += __shfl_xor_sync(0xFFFFFFFFu, sB, off);
    }
    const float invA = __fdividef(1.0f, sA);
    const float invB = __fdividef(1.0f, sB);
    float* pwA = &ps[(2 * w) * 200];
    float* pwB = pwA + 200;
#pragma unroll
    for (int j = 0; j < 7; j++) {
        const int k = lane + 32 * j;
        if (k < GRID_N) {
            pwA[k] = attA[j] * invA;
            pwB[k] = attB[j] * invB;
        }
    }
    __syncwarp();

    // ---- pass 2: sigmoid-gated PV, K/V reads shared by both queries ----
    const float qA0 = qrowA[2 * lane], qA1 = qrowA[2 * lane + 1];
    const float qB0 = qrowB[2 * lane], qB1 = qrowB[2 * lane + 1];
    float aAx = 0.f, aAy = 0.f, aBx = 0.f, aBy = 0.f;
#pragma unroll 4
    for (int k = 0; k < GRID_N; k++) {
        const float  pA = pwA[k];
        const float  pB = pwB[k];
        const float2 kv = *(const float2*)&kp[k * KST + 2 * lane];
        const float2 vv = *(const float2*)&vp[k * VST + 2 * lane];
        const float sA0 = sigm_fast(qA0 * kv.x);
        const float sA1 = sigm_fast(qA1 * kv.y);
        const float sB0 = sigm_fast(qB0 * kv.x);
        const float sB1 = sigm_fast(qB1 * kv.y);
        aAx = fmaf(pA, sA0 * vv.x, aAx);
        aAy = fmaf(pA, sA1 * vv.y, aAy);
        aBx = fmaf(pB, sB0 * vv.x, aBx);
        aBy = fmaf(pB, sB1 * vv.y, aBy);
    }
    float2 rA; rA.x = aAx; rA.y = aAy;
    float2 rB; rB.x = aBx; rB.y = aBy;
    *(float2*)&g_img[(b * GRID_N + qA) * DM + hbase + 2 * lane] = rA;
    *(float2*)&g_img[(b * GRID_N + qB) * DM + hbase + 2 * lane] = rB;
}

// ============================================================
extern "C" void kernel_launch(void* const* d_in, const int* in_sizes, int n_in,
                              void* d_out, int out_size) {
    (void)in_sizes; (void)n_in; (void)out_size;
    const float* queries = (const float*)d_in[0];
    const float* keys    = (const float*)d_in[1];
    const float* values  = (const float*)d_in[2];
    const float* Wq = (const float*)d_in[3];
    const float* bq = (const float*)d_in[4];
    const float* Wk = (const float*)d_in[5];
    const float* bk = (const float*)d_in[6];
    const float* Wv = (const float*)d_in[7];
    const float* bv = (const float*)d_in[8];
    const float* Wo = (const float*)d_in[9];
    const float* bo = (const float*)d_in[10];
    const float* scale = (const float*)d_in[11];
    float* out = (float*)d_out;

    void *p_qsig, *p_kp, *p_vp, *p_img;
    cudaGetSymbolAddress(&p_qsig, g_qsig);
    cudaGetSymbolAddress(&p_kp,   g_kp);
    cudaGetSymbolAddress(&p_vp,   g_vp);
    cudaGetSymbolAddress(&p_img,  g_img);

    const int attn_smem = ATTN_SMEM_FLOATS * (int)sizeof(float);
    cudaFuncSetAttribute(attn_kernel,
                         cudaFuncAttributeMaxDynamicSharedMemorySize, attn_smem);

    dim3 pgrid((ROWS + GTM - 1) / GTM, DM / GTN, 3);  // (25, 8, 3) = 600
    proj3_kernel<<<pgrid, GTHREADS>>>(queries, keys, values,
                                      Wq, Wk, Wv, bq, bk, bv,
                                      (float*)p_qsig, (float*)p_kp, (float*)p_vp);

    dim3 agrid(GRID_N / QT, NH, BB);                  // (14, 8, 4) = 448
    attn_kernel<<<agrid, NT, attn_smem>>>(scale);

    dim3 ogrid((ROWS + GTM - 1) / GTM, DM / GTN, 1);  // (25, 8) = 200
    gemm_out_kernel<<<ogrid, GTHREADS>>>((const float*)p_img, Wo, bo, out,
                                         (const float*)p_qsig);
}

// round 10
// speedup vs baseline: 2.1048x; 1.1958x over previous
#include <cuda_runtime.h>
#include <math_constants.h>
#include <cstdint>

#define BB 4
#define GRID_N 196
#define DM 512
#define NH 8
#define DK 64
#define ROWS (BB * GRID_N)   // 784
#define XS (ROWS * DM)       // 401408
#define WS (DM * DM)         // 262144

typedef unsigned long long ull;

// ---- scratch (no allocations allowed) ----
__device__ float g_qsig[XS];
__device__ float g_kp[XS];
__device__ float g_vp[XS];
__device__ float g_img[XS];
__device__ float g_x32[3 * XS];   // tf32-rounded inputs
__device__ float g_w32[4 * WS];   // tf32-rounded Wq,Wk,Wv,Wo

__device__ __forceinline__ float sigm_exact(float x) {
    return __fdividef(1.0f, 1.0f + __expf(-x));
}
__device__ __forceinline__ float to_tf32(float x) {
    unsigned r;
    asm("cvt.rna.tf32.f32 %0, %1;" : "=r"(r) : "f"(x));
    return __uint_as_float(r);
}
__device__ __forceinline__ ull pk2(float lo, float hi) {
    ull r;
    asm("mov.b64 %0, {%1, %2};" : "=l"(r) : "f"(lo), "f"(hi));
    return r;
}
__device__ __forceinline__ ull mul2(ull a, ull b) {
    ull d;
    asm("mul.rn.f32x2 %0, %1, %2;" : "=l"(d) : "l"(a), "l"(b));
    return d;
}
__device__ __forceinline__ ull fma2(ull a, ull b, ull c) {
    ull d;
    asm("fma.rn.f32x2 %0, %1, %2, %3;" : "=l"(d) : "l"(a), "l"(b), "l"(c));
    return d;
}
__device__ __forceinline__ float tanh_fast(float x) {
    float t;
    asm("tanh.approx.f32 %0, %1;" : "=f"(t) : "f"(x));
    return t;
}

// ============================================================
// prep: round-to-nearest tf32 copies of inputs + weights
// ============================================================
__global__ void __launch_bounds__(256)
prep_kernel(const float* q, const float* k, const float* v,
            const float* wq, const float* wk, const float* wv, const float* wo) {
    const int z = blockIdx.y;
    const float* src; float* dst; int n4;
    if (z < 3) {
        src = (z == 0) ? q : ((z == 1) ? k : v);
        dst = g_x32 + z * XS;
        n4 = XS / 4;
    } else {
        const int i = z - 3;
        src = (i == 0) ? wq : ((i == 1) ? wk : ((i == 2) ? wv : wo));
        dst = g_w32 + i * WS;
        n4 = WS / 4;
    }
    const int i4 = blockIdx.x * 256 + threadIdx.x;
    if (i4 < n4) {
        float4 t = ((const float4*)src)[i4];
        t.x = to_tf32(t.x); t.y = to_tf32(t.y);
        t.z = to_tf32(t.z); t.w = to_tf32(t.w);
        ((float4*)dst)[i4] = t;
    }
}

// ============================================================
// TF32 tensor-core GEMM: out[r,j] = sum_c X[r,c]*W[j,c] + bias[j]
// 64x64 CTA tile, 4 warps (2x2), warp tile 32x32 via m16n8k8.
// X,W must be tf32-rounded already. EPILOGUE 1: sigmoid gating.
// ============================================================
#define GKC 32
#define GNCH (DM / GKC)   // 16

__device__ __forceinline__ void mma_tf32(float* d, const unsigned* a, const unsigned* b) {
    asm volatile(
        "mma.sync.aligned.m16n8k8.row.col.f32.tf32.tf32.f32 "
        "{%0,%1,%2,%3}, {%4,%5,%6,%7}, {%8,%9}, {%0,%1,%2,%3};"
        : "+f"(d[0]), "+f"(d[1]), "+f"(d[2]), "+f"(d[3])
        : "r"(a[0]), "r"(a[1]), "r"(a[2]), "r"(a[3]),
          "r"(b[0]), "r"(b[1]));
}

template <int EPILOGUE>
__device__ __forceinline__ void gemm_tf32_tile(const float* __restrict__ X,
                                               const float* __restrict__ W,
                                               const float* __restrict__ bias,
                                               float* __restrict__ out,
                                               const float* __restrict__ qsig) {
    __shared__ __align__(16) float As[2][64][36];
    __shared__ __align__(16) float Bs[2][64][36];

    const int t    = threadIdx.x;
    const int lane = t & 31;
    const int warp = t >> 5;
    const int g    = lane >> 2;   // 0..7
    const int qq   = lane & 3;    // 0..3
    const int wm   = (warp >> 1) * 32;
    const int wn   = (warp & 1) * 32;
    const int r0   = blockIdx.x * 64;
    const int j0   = blockIdx.y * 64;

    const int lrow = t >> 3;         // 0..15
    const int lc4  = (t & 7) << 2;   // 0..28
    const float* Xp[4]; const float* Wp[4];
#pragma unroll
    for (int i = 0; i < 4; i++) {
        const int row = lrow + i * 16;
        Xp[i] = &X[min(r0 + row, ROWS - 1) * DM + lc4];
        Wp[i] = &W[(j0 + row) * DM + lc4];
    }

    float acc[2][4][4];
#pragma unroll
    for (int i = 0; i < 2; i++)
#pragma unroll
        for (int j = 0; j < 4; j++)
#pragma unroll
            for (int e = 0; e < 4; e++) acc[i][j][e] = 0.0f;

    // preload chunk 0
#pragma unroll
    for (int i = 0; i < 4; i++) {
        *(float4*)&As[0][lrow + i * 16][lc4] = *(const float4*)Xp[i];
        *(float4*)&Bs[0][lrow + i * 16][lc4] = *(const float4*)Wp[i];
    }
    __syncthreads();

    int buf = 0;
#pragma unroll 1
    for (int c = 0; c < GNCH; c++) {
        float4 xr[4], wr[4];
        const bool more = (c + 1 < GNCH);
        if (more) {
#pragma unroll
            for (int i = 0; i < 4; i++) {
                xr[i] = *(const float4*)(Xp[i] + (c + 1) * GKC);
                wr[i] = *(const float4*)(Wp[i] + (c + 1) * GKC);
            }
        }
#pragma unroll
        for (int kk = 0; kk < GKC; kk += 8) {
            unsigned a[2][4], b[4][2];
#pragma unroll
            for (int i = 0; i < 2; i++) {
                const int mr = wm + i * 16 + g;
                a[i][0] = __float_as_uint(As[buf][mr][kk + qq]);
                a[i][1] = __float_as_uint(As[buf][mr + 8][kk + qq]);
                a[i][2] = __float_as_uint(As[buf][mr][kk + qq + 4]);
                a[i][3] = __float_as_uint(As[buf][mr + 8][kk + qq + 4]);
            }
#pragma unroll
            for (int j = 0; j < 4; j++) {
                const int nr = wn + j * 8 + g;
                b[j][0] = __float_as_uint(Bs[buf][nr][kk + qq]);
                b[j][1] = __float_as_uint(Bs[buf][nr][kk + qq + 4]);
            }
#pragma unroll
            for (int i = 0; i < 2; i++)
#pragma unroll
                for (int j = 0; j < 4; j++)
                    mma_tf32(acc[i][j], a[i], b[j]);
        }
        if (more) {
            const int nb = buf ^ 1;
#pragma unroll
            for (int i = 0; i < 4; i++) {
                *(float4*)&As[nb][lrow + i * 16][lc4] = xr[i];
                *(float4*)&Bs[nb][lrow + i * 16][lc4] = wr[i];
            }
            __syncthreads();
            buf = nb;
        }
    }

    // epilogue: c0,c1 -> row g; c2,c3 -> row g+8
#pragma unroll
    for (int i = 0; i < 2; i++) {
#pragma unroll
        for (int j = 0; j < 4; j++) {
            const int jc = j0 + wn + j * 8 + 2 * qq;
            const float2 bb = *(const float2*)&bias[jc];
#pragma unroll
            for (int h = 0; h < 2; h++) {
                const int r = r0 + wm + i * 16 + g + h * 8;
                if (r < ROWS) {
                    float ox = acc[i][j][h * 2 + 0] + bb.x;
                    float oy = acc[i][j][h * 2 + 1] + bb.y;
                    if (EPILOGUE == 1) {
                        const float2 qv = *(const float2*)&qsig[r * DM + jc];
                        ox *= sigm_exact(qv.x * ox);
                        oy *= sigm_exact(qv.y * oy);
                    }
                    float2 o; o.x = ox; o.y = oy;
                    *(float2*)&out[r * DM + jc] = o;
                }
            }
        }
    }
}

__global__ void __launch_bounds__(128)
proj3_kernel(const float* bq, const float* bk, const float* bv) {
    const float* X; const float* W; const float* B; float* O;
    if (blockIdx.z == 0)      { X = g_x32;          W = g_w32;          B = bq; O = g_qsig; }
    else if (blockIdx.z == 1) { X = g_x32 + XS;     W = g_w32 + WS;     B = bk; O = g_kp; }
    else                      { X = g_x32 + 2 * XS; W = g_w32 + 2 * WS; B = bv; O = g_vp; }
    gemm_tf32_tile<0>(X, W, B, O, nullptr);
}

__global__ void __launch_bounds__(128)
gemm_out_kernel(const float* __restrict__ bias, float* __restrict__ out) {
    gemm_tf32_tile<1>(g_img, g_w32 + 3 * WS, bias, out, g_qsig);
}

// ============================================================
// Fused attention core — 2 queries per warp, q-tile 14 (7 warps).
// pass 2 uses packed f32x2 FMA; MUFU.TANH sigmoid.
// ============================================================
#define QT 14
#define NW 7
#define NT (NW * 32)
#define KST 66
#define VST 64
#define ATTN_SMEM_FLOATS (GRID_N * KST + GRID_N * VST + QT * 64 + QT * 200)

__global__ void __launch_bounds__(NT)
attn_kernel(const float* __restrict__ scale) {
    extern __shared__ float sm[];
    float* kp = sm;
    float* vp = kp + GRID_N * KST;
    float* qs = vp + GRID_N * VST;
    float* ps = qs + QT * 64;

    const int t  = threadIdx.x;
    const int q0 = blockIdx.x * QT;
    const int h  = blockIdx.y;
    const int b  = blockIdx.z;
    const int hbase = h * DK;

    for (int idx = t; idx < GRID_N * 16; idx += NT) {
        const int s  = idx >> 4;
        const int d4 = (idx & 15) << 2;
        const int g  = (b * GRID_N + s) * DM + hbase + d4;
        const float4 kv = *(const float4*)&g_kp[g];
        const float4 vv = *(const float4*)&g_vp[g];
        float* kd = &kp[s * KST + d4];
        kd[0] = kv.x; kd[1] = kv.y; kd[2] = kv.z; kd[3] = kv.w;
        float* vd = &vp[s * VST + d4];
        vd[0] = vv.x; vd[1] = vv.y; vd[2] = vv.z; vd[3] = vv.w;
    }
    for (int idx = t; idx < QT * 64; idx += NT) {
        const int w = idx >> 6;
        const int d = idx & 63;
        qs[idx] = g_qsig[(b * GRID_N + q0 + w) * DM + hbase + d];
    }
    __syncthreads();

    const int w    = t >> 5;
    const int lane = t & 31;
    const int qA   = q0 + 2 * w;
    const int qB   = qA + 1;
    const float* qrowA = &qs[(2 * w) * 64];
    const float* qrowB = qrowA + 64;

    // ---- pass 1 ----
    const float* rp[7];
#pragma unroll
    for (int j = 0; j < 7; j++) {
        const int k = lane + 32 * j;
        rp[j] = &kp[(k < GRID_N ? k : GRID_N - 1) * KST];
    }
    float attA[7], attB[7];
#pragma unroll
    for (int j = 0; j < 7; j++) { attA[j] = 0.0f; attB[j] = 0.0f; }

#pragma unroll 8
    for (int d = 0; d < 64; d += 2) {
        const float2 qa = *(const float2*)&qrowA[d];
        const float2 qb = *(const float2*)&qrowB[d];
#pragma unroll
        for (int j = 0; j < 7; j++) {
            const float2 kv = *(const float2*)&rp[j][d];
            attA[j] = fmaf(qa.x, kv.x, fmaf(qa.y, kv.y, attA[j]));
            attB[j] = fmaf(qb.x, kv.x, fmaf(qb.y, kv.y, attB[j]));
        }
    }
    const float* srowA = &scale[(h * GRID_N + qA) * GRID_N];
    const float* srowB = &scale[(h * GRID_N + qB) * GRID_N];
#pragma unroll
    for (int j = 0; j < 7; j++) {
        const int k = lane + 32 * j;
        if (k < GRID_N) {
            attA[j] *= srowA[k];
            attB[j] *= srowB[k];
        } else {
            attA[j] = -CUDART_INF_F;
            attB[j] = -CUDART_INF_F;
        }
    }

    // ---- softmax ----
    float mA = attA[0], mB = attB[0];
#pragma unroll
    for (int j = 1; j < 7; j++) { mA = fmaxf(mA, attA[j]); mB = fmaxf(mB, attB[j]); }
#pragma unroll
    for (int off = 16; off > 0; off >>= 1) {
        mA = fmaxf(mA, __shfl_xor_sync(0xFFFFFFFFu, mA, off));
        mB = fmaxf(mB, __shfl_xor_sync(0xFFFFFFFFu, mB, off));
    }
    float sA = 0.0f, sB = 0.0f;
#pragma unroll
    for (int j = 0; j < 7; j++) {
        attA[j] = __expf(attA[j] - mA); sA += attA[j];
        attB[j] = __expf(attB[j] - mB); sB += attB[j];
    }
#pragma unroll
    for (int off = 16; off > 0; off >>= 1) {
        sA += __shfl_xor_sync(0xFFFFFFFFu, sA, off);
        sB += __shfl_xor_sync(0xFFFFFFFFu, sB, off);
    }
    const float invA = __fdividef(1.0f, sA);
    const float invB = __fdividef(1.0f, sB);
    float* pwA = &ps[(2 * w) * 200];
    float* pwB = pwA + 200;
#pragma unroll
    for (int j = 0; j < 7; j++) {
        const int k = lane + 32 * j;
        if (k < GRID_N) {
            pwA[k] = attA[j] * invA;
            pwB[k] = attB[j] * invB;
        }
    }
    __syncwarp();

    // ---- pass 2: packed f32x2; sigmoid = 0.5*tanh(0.5x)+0.5 ----
    const float qA0 = 0.5f * qrowA[2 * lane], qA1 = 0.5f * qrowA[2 * lane + 1];
    const float qB0 = 0.5f * qrowB[2 * lane], qB1 = 0.5f * qrowB[2 * lane + 1];
    const ull halfs = pk2(0.5f, 0.5f);
    ull accA = pk2(0.0f, 0.0f), accB = accA;
#pragma unroll 4
    for (int k = 0; k < GRID_N; k++) {
        const float pA = pwA[k];
        const float pB = pwB[k];
        const float2 kv = *(const float2*)&kp[k * KST + 2 * lane];
        const ull vv2 = *(const ull*)&vp[k * VST + 2 * lane];
        const float tA0 = tanh_fast(qA0 * kv.x);
        const float tA1 = tanh_fast(qA1 * kv.y);
        const float tB0 = tanh_fast(qB0 * kv.x);
        const float tB1 = tanh_fast(qB1 * kv.y);
        const ull gA = fma2(pk2(tA0, tA1), halfs, halfs);
        const ull gB = fma2(pk2(tB0, tB1), halfs, halfs);
        accA = fma2(pk2(pA, pA), mul2(gA, vv2), accA);
        accB = fma2(pk2(pB, pB), mul2(gB, vv2), accB);
    }
    float aAx, aAy, aBx, aBy;
    asm("mov.b64 {%0, %1}, %2;" : "=f"(aAx), "=f"(aAy) : "l"(accA));
    asm("mov.b64 {%0, %1}, %2;" : "=f"(aBx), "=f"(aBy) : "l"(accB));
    // store tf32-rounded (out-gemm consumes img as tf32 A operand)
    float2 rA; rA.x = to_tf32(aAx); rA.y = to_tf32(aAy);
    float2 rB; rB.x = to_tf32(aBx); rB.y = to_tf32(aBy);
    *(float2*)&g_img[(b * GRID_N + qA) * DM + hbase + 2 * lane] = rA;
    *(float2*)&g_img[(b * GRID_N + qB) * DM + hbase + 2 * lane] = rB;
}

// ============================================================
extern "C" void kernel_launch(void* const* d_in, const int* in_sizes, int n_in,
                              void* d_out, int out_size) {
    (void)in_sizes; (void)n_in; (void)out_size;
    const float* queries = (const float*)d_in[0];
    const float* keys    = (const float*)d_in[1];
    const float* values  = (const float*)d_in[2];
    const float* Wq = (const float*)d_in[3];
    const float* bq = (const float*)d_in[4];
    const float* Wk = (const float*)d_in[5];
    const float* bk = (const float*)d_in[6];
    const float* Wv = (const float*)d_in[7];
    const float* bv = (const float*)d_in[8];
    const float* Wo = (const float*)d_in[9];
    const float* bo = (const float*)d_in[10];
    const float* scale = (const float*)d_in[11];
    float* out = (float*)d_out;

    const int attn_smem = ATTN_SMEM_FLOATS * (int)sizeof(float);
    cudaFuncSetAttribute(attn_kernel,
                         cudaFuncAttributeMaxDynamicSharedMemorySize, attn_smem);

    // tf32 rounding pass (inputs + weights)
    dim3 prgrid((XS / 4 + 255) / 256, 7);
    prep_kernel<<<prgrid, 256>>>(queries, keys, values, Wq, Wk, Wv, Wo);

    // projections (tensor core)
    dim3 pgrid((ROWS + 63) / 64, DM / 64, 3);   // (13, 8, 3)
    proj3_kernel<<<pgrid, 128>>>(bq, bk, bv);

    // fused attention core
    dim3 agrid(GRID_N / QT, NH, BB);            // (14, 8, 4)
    attn_kernel<<<agrid, NT, attn_smem>>>(scale);

    // output projection + gating (tensor core)
    dim3 ogrid((ROWS + 63) / 64, DM / 64, 1);   // (13, 8)
    gemm_out_kernel<<<ogrid, 128>>>(bo, out);
}

// round 12
// speedup vs baseline: 2.1055x; 1.0004x over previous
#include <cuda_runtime.h>
#include <math_constants.h>
#include <cstdint>

#define BB 4
#define GRID_N 196
#define DM 512
#define NH 8
#define DK 64
#define ROWS (BB * GRID_N)   // 784
#define XS (ROWS * DM)

typedef unsigned long long ull;

// ---- scratch (no allocations allowed) ----
__device__ float g_qsig[XS];
__device__ float g_kp[XS];
__device__ float g_vp[XS];
__device__ float g_img[XS];

__device__ __forceinline__ float sigm_exact(float x) {
    return __fdividef(1.0f, 1.0f + __expf(-x));
}
__device__ __forceinline__ float to_tf32(float x) {
    unsigned r;
    asm("cvt.rna.tf32.f32 %0, %1;" : "=r"(r) : "f"(x));
    return __uint_as_float(r);
}
__device__ __forceinline__ ull pk2(float lo, float hi) {
    ull r;
    asm("mov.b64 %0, {%1, %2};" : "=l"(r) : "f"(lo), "f"(hi));
    return r;
}
__device__ __forceinline__ ull mul2(ull a, ull b) {
    ull d;
    asm("mul.rn.f32x2 %0, %1, %2;" : "=l"(d) : "l"(a), "l"(b));
    return d;
}
__device__ __forceinline__ ull fma2(ull a, ull b, ull c) {
    ull d;
    asm("fma.rn.f32x2 %0, %1, %2, %3;" : "=l"(d) : "l"(a), "l"(b), "l"(c));
    return d;
}
__device__ __forceinline__ float tanh_fast(float x) {
    float t;
    asm("tanh.approx.f32 %0, %1;" : "=f"(t) : "f"(x));
    return t;
}

// ============================================================
// TF32 tensor-core GEMM with fragment-layout shared memory.
// out[r,j] = sum_c X[r,c]*W[j,c] + bias[j]   (cvt fused in loader)
// 64x64 CTA tile, 256 thr (8 warps, 2x4), warp tile 32x16, m16n8k8.
// Smem holds fragments in consumer order:
//   A: [kstep][mtile(4)][lane(32)][4]  (kstep stride 516)
//   B: [kstep][ntile(8)][lane(32)][2]  (kstep stride 514)
// so each a-frag is one LDS.128 and each b-frag one LDS.64.
// ============================================================
#define KC 32
#define NCH (DM / KC)   // 16
#define AF_K 516
#define BF_K 514
#define AF_SZ (4 * AF_K)
#define BF_SZ (4 * BF_K)

__device__ __forceinline__ void mma_tf32(float* d, const unsigned* a, const unsigned* b) {
    asm volatile(
        "mma.sync.aligned.m16n8k8.row.col.f32.tf32.tf32.f32 "
        "{%0,%1,%2,%3}, {%4,%5,%6,%7}, {%8,%9}, {%0,%1,%2,%3};"
        : "+f"(d[0]), "+f"(d[1]), "+f"(d[2]), "+f"(d[3])
        : "r"(a[0]), "r"(a[1]), "r"(a[2]), "r"(a[3]),
          "r"(b[0]), "r"(b[1]));
}

__device__ __forceinline__ void stA(float* dst, float4 v) {
    dst[0]  = to_tf32(v.x); dst[4]  = to_tf32(v.y);
    dst[8]  = to_tf32(v.z); dst[12] = to_tf32(v.w);
}
__device__ __forceinline__ void stB(float* dst, float4 v) {
    dst[0] = to_tf32(v.x); dst[2] = to_tf32(v.y);
    dst[4] = to_tf32(v.z); dst[6] = to_tf32(v.w);
}

template <int EPILOGUE>
__device__ __forceinline__ void gemm_tf32_tile(const float* __restrict__ X,
                                               const float* __restrict__ W,
                                               const float* __restrict__ bias,
                                               float* __restrict__ out,
                                               const float* __restrict__ qsig) {
    __shared__ __align__(16) float Af[2][AF_SZ];
    __shared__ __align__(16) float Bf[2][BF_SZ];

    const int t    = threadIdx.x;
    const int lane = t & 31;
    const int warp = t >> 5;
    const int g    = lane >> 2;     // 0..7
    const int qq   = lane & 3;      // 0..3
    const int wm   = (warp >> 2) * 32;   // 0,32
    const int wn   = (warp & 3) * 16;    // 0,16,32,48
    const int r0   = blockIdx.x * 64;
    const int j0   = blockIdx.y * 64;

    // loader geometry: element e = t + i*256 -> (row = e>>3, colgroup = e&7)
    const float* Xp[2]; int adst[2];
    const float* Wp[2]; int bdst[2];
#pragma unroll
    for (int i = 0; i < 2; i++) {
        const int e   = t + i * 256;
        const int row = e >> 3;
        const int cg  = e & 7;
        Xp[i] = &X[min(r0 + row, ROWS - 1) * DM + cg * 4];
        adst[i] = (cg >> 1) * AF_K + (row >> 4) * 128 + (row & 7) * 16
                + ((row >> 3) & 1) + (cg & 1) * 2;
        Wp[i] = &W[(j0 + row) * DM + cg * 4];
        bdst[i] = (cg >> 1) * BF_K + (row >> 3) * 64 + (row & 7) * 8 + (cg & 1);
    }

    float acc[2][2][4];
#pragma unroll
    for (int i = 0; i < 2; i++)
#pragma unroll
        for (int j = 0; j < 2; j++)
#pragma unroll
            for (int e = 0; e < 4; e++) acc[i][j][e] = 0.0f;

    // preload chunk 0 -> buffer 0
#pragma unroll
    for (int i = 0; i < 2; i++) {
        stA(&Af[0][adst[i]], *(const float4*)Xp[i]);
        stB(&Bf[0][bdst[i]], *(const float4*)Wp[i]);
    }
    __syncthreads();

    const int amt = (wm >> 4);   // mtile base: 0 or 2
    const int bnt = (wn >> 3);   // ntile base: 0,2,4,6

    int buf = 0;
#pragma unroll 1
    for (int c = 0; c < NCH; c++) {
        float4 xr[2], wr[2];
        const bool more = (c + 1 < NCH);
        if (more) {
#pragma unroll
            for (int i = 0; i < 2; i++) {
                xr[i] = *(const float4*)(Xp[i] + (c + 1) * KC);
                wr[i] = *(const float4*)(Wp[i] + (c + 1) * KC);
            }
        }
#pragma unroll
        for (int ks = 0; ks < 4; ks++) {
            unsigned a[2][4], b[2][2];
#pragma unroll
            for (int i = 0; i < 2; i++) {
                const float4 av = *(const float4*)&Af[buf][ks * AF_K + (amt + i) * 128 + lane * 4];
                a[i][0] = __float_as_uint(av.x); a[i][1] = __float_as_uint(av.y);
                a[i][2] = __float_as_uint(av.z); a[i][3] = __float_as_uint(av.w);
            }
#pragma unroll
            for (int j = 0; j < 2; j++) {
                const float2 bv = *(const float2*)&Bf[buf][ks * BF_K + (bnt + j) * 64 + lane * 2];
                b[j][0] = __float_as_uint(bv.x); b[j][1] = __float_as_uint(bv.y);
            }
#pragma unroll
            for (int i = 0; i < 2; i++)
#pragma unroll
                for (int j = 0; j < 2; j++)
                    mma_tf32(acc[i][j], a[i], b[j]);
        }
        if (more) {
            const int nb = buf ^ 1;
            __syncthreads();   // all reads of buf done before overwrite of nb==old? (nb is the other buffer; sync guards reuse below)
#pragma unroll
            for (int i = 0; i < 2; i++) {
                stA(&Af[nb][adst[i]], xr[i]);
                stB(&Bf[nb][bdst[i]], wr[i]);
            }
            __syncthreads();
            buf = nb;
        }
    }

    // epilogue
#pragma unroll
    for (int i = 0; i < 2; i++) {
#pragma unroll
        for (int j = 0; j < 2; j++) {
            const int jc = j0 + wn + j * 8 + 2 * qq;
            const float2 bb = *(const float2*)&bias[jc];
#pragma unroll
            for (int h = 0; h < 2; h++) {
                const int r = r0 + wm + i * 16 + g + h * 8;
                if (r < ROWS) {
                    float ox = acc[i][j][h * 2 + 0] + bb.x;
                    float oy = acc[i][j][h * 2 + 1] + bb.y;
                    if (EPILOGUE == 1) {
                        const float2 qv = *(const float2*)&qsig[r * DM + jc];
                        ox *= sigm_exact(qv.x * ox);
                        oy *= sigm_exact(qv.y * oy);
                    }
                    float2 o; o.x = ox; o.y = oy;
                    *(float2*)&out[r * DM + jc] = o;
                }
            }
        }
    }
}

__global__ void __launch_bounds__(256, 2)
proj3_kernel(const float* Xq, const float* Xk, const float* Xv,
             const float* Wq, const float* Wk, const float* Wv,
             const float* bq, const float* bk, const float* bv) {
    const float* X; const float* W; const float* B; float* O;
    if (blockIdx.z == 0)      { X = Xq; W = Wq; B = bq; O = g_qsig; }
    else if (blockIdx.z == 1) { X = Xk; W = Wk; B = bk; O = g_kp; }
    else                      { X = Xv; W = Wv; B = bv; O = g_vp; }
    gemm_tf32_tile<0>(X, W, B, O, nullptr);
}

__global__ void __launch_bounds__(256, 2)
gemm_out_kernel(const float* __restrict__ Wo, const float* __restrict__ bias,
                float* __restrict__ out) {
    gemm_tf32_tile<1>(g_img, Wo, bias, out, g_qsig);
}

// ============================================================
// Fused attention core — 2 queries per warp, q-tile 14 (7 warps).
// pass 2 uses packed f32x2 FMA; MUFU.TANH sigmoid.
// ============================================================
#define QT 14
#define NW 7
#define NT (NW * 32)
#define KST 66
#define VST 64
#define ATTN_SMEM_FLOATS (GRID_N * KST + GRID_N * VST + QT * 64 + QT * 200)

__global__ void __launch_bounds__(NT)
attn_kernel(const float* __restrict__ scale) {
    extern __shared__ float sm[];
    float* kp = sm;
    float* vp = kp + GRID_N * KST;
    float* qs = vp + GRID_N * VST;
    float* ps = qs + QT * 64;

    const int t  = threadIdx.x;
    const int q0 = blockIdx.x * QT;
    const int h  = blockIdx.y;
    const int b  = blockIdx.z;
    const int hbase = h * DK;

    for (int idx = t; idx < GRID_N * 16; idx += NT) {
        const int s  = idx >> 4;
        const int d4 = (idx & 15) << 2;
        const int g  = (b * GRID_N + s) * DM + hbase + d4;
        const float4 kv = *(const float4*)&g_kp[g];
        const float4 vv = *(const float4*)&g_vp[g];
        float* kd = &kp[s * KST + d4];
        kd[0] = kv.x; kd[1] = kv.y; kd[2] = kv.z; kd[3] = kv.w;
        float* vd = &vp[s * VST + d4];
        vd[0] = vv.x; vd[1] = vv.y; vd[2] = vv.z; vd[3] = vv.w;
    }
    for (int idx = t; idx < QT * 64; idx += NT) {
        const int w = idx >> 6;
        const int d = idx & 63;
        qs[idx] = g_qsig[(b * GRID_N + q0 + w) * DM + hbase + d];
    }
    __syncthreads();

    const int w    = t >> 5;
    const int lane = t & 31;
    const int qA   = q0 + 2 * w;
    const int qB   = qA + 1;
    const float* qrowA = &qs[(2 * w) * 64];
    const float* qrowB = qrowA + 64;

    // ---- pass 1 ----
    const float* rp[7];
#pragma unroll
    for (int j = 0; j < 7; j++) {
        const int k = lane + 32 * j;
        rp[j] = &kp[(k < GRID_N ? k : GRID_N - 1) * KST];
    }
    float attA[7], attB[7];
#pragma unroll
    for (int j = 0; j < 7; j++) { attA[j] = 0.0f; attB[j] = 0.0f; }

#pragma unroll 8
    for (int d = 0; d < 64; d += 2) {
        const float2 qa = *(const float2*)&qrowA[d];
        const float2 qb = *(const float2*)&qrowB[d];
#pragma unroll
        for (int j = 0; j < 7; j++) {
            const float2 kv = *(const float2*)&rp[j][d];
            attA[j] = fmaf(qa.x, kv.x, fmaf(qa.y, kv.y, attA[j]));
            attB[j] = fmaf(qb.x, kv.x, fmaf(qb.y, kv.y, attB[j]));
        }
    }
    const float* srowA = &scale[(h * GRID_N + qA) * GRID_N];
    const float* srowB = &scale[(h * GRID_N + qB) * GRID_N];
#pragma unroll
    for (int j = 0; j < 7; j++) {
        const int k = lane + 32 * j;
        if (k < GRID_N) {
            attA[j] *= srowA[k];
            attB[j] *= srowB[k];
        } else {
            attA[j] = -CUDART_INF_F;
            attB[j] = -CUDART_INF_F;
        }
    }

    // ---- softmax ----
    float mA = attA[0], mB = attB[0];
#pragma unroll
    for (int j = 1; j < 7; j++) { mA = fmaxf(mA, attA[j]); mB = fmaxf(mB, attB[j]); }
#pragma unroll
    for (int off = 16; off > 0; off >>= 1) {
        mA = fmaxf(mA, __shfl_xor_sync(0xFFFFFFFFu, mA, off));
        mB = fmaxf(mB, __shfl_xor_sync(0xFFFFFFFFu, mB, off));
    }
    float sA = 0.0f, sB = 0.0f;
#pragma unroll
    for (int j = 0; j < 7; j++) {
        attA[j] = __expf(attA[j] - mA); sA += attA[j];
        attB[j] = __expf(attB[j] - mB); sB += attB[j];
    }
#pragma unroll
    for (int off = 16; off > 0; off >>= 1) {
        sA += __shfl_xor_sync(0xFFFFFFFFu, sA, off);
        sB += __shfl_xor_sync(0xFFFFFFFFu, sB, off);
    }
    const float invA = __fdividef(1.0f, sA);
    const float invB = __fdividef(1.0f, sB);
    float* pwA = &ps[(2 * w) * 200];
    float* pwB = pwA + 200;
#pragma unroll
    for (int j = 0; j < 7; j++) {
        const int k = lane + 32 * j;
        if (k < GRID_N) {
            pwA[k] = attA[j] * invA;
            pwB[k] = attB[j] * invB;
        }
    }
    __syncwarp();

    // ---- pass 2 ----
    const float qA0 = 0.5f * qrowA[2 * lane], qA1 = 0.5f * qrowA[2 * lane + 1];
    const float qB0 = 0.5f * qrowB[2 * lane], qB1 = 0.5f * qrowB[2 * lane + 1];
    const ull halfs = pk2(0.5f, 0.5f);
    ull accA = pk2(0.0f, 0.0f), accB = accA;
#pragma unroll 4
    for (int k = 0; k < GRID_N; k++) {
        const float pA = pwA[k];
        const float pB = pwB[k];
        const float2 kv = *(const float2*)&kp[k * KST + 2 * lane];
        const ull vv2 = *(const ull*)&vp[k * VST + 2 * lane];
        const float tA0 = tanh_fast(qA0 * kv.x);
        const float tA1 = tanh_fast(qA1 * kv.y);
        const float tB0 = tanh_fast(qB0 * kv.x);
        const float tB1 = tanh_fast(qB1 * kv.y);
        const ull gA = fma2(pk2(tA0, tA1), halfs, halfs);
        const ull gB = fma2(pk2(tB0, tB1), halfs, halfs);
        accA = fma2(pk2(pA, pA), mul2(gA, vv2), accA);
        accB = fma2(pk2(pB, pB), mul2(gB, vv2), accB);
    }
    float aAx, aAy, aBx, aBy;
    asm("mov.b64 {%0, %1}, %2;" : "=f"(aAx), "=f"(aAy) : "l"(accA));
    asm("mov.b64 {%0, %1}, %2;" : "=f"(aBx), "=f"(aBy) : "l"(accB));
    float2 rA; rA.x = aAx; rA.y = aAy;
    float2 rB; rB.x = aBx; rB.y = aBy;
    *(float2*)&g_img[(b * GRID_N + qA) * DM + hbase + 2 * lane] = rA;
    *(float2*)&g_img[(b * GRID_N + qB) * DM + hbase + 2 * lane] = rB;
}

// ============================================================
extern "C" void kernel_launch(void* const* d_in, const int* in_sizes, int n_in,
                              void* d_out, int out_size) {
    (void)in_sizes; (void)n_in; (void)out_size;
    const float* queries = (const float*)d_in[0];
    const float* keys    = (const float*)d_in[1];
    const float* values  = (const float*)d_in[2];
    const float* Wq = (const float*)d_in[3];
    const float* bq = (const float*)d_in[4];
    const float* Wk = (const float*)d_in[5];
    const float* bk = (const float*)d_in[6];
    const float* Wv = (const float*)d_in[7];
    const float* bv = (const float*)d_in[8];
    const float* Wo = (const float*)d_in[9];
    const float* bo = (const float*)d_in[10];
    const float* scale = (const float*)d_in[11];
    float* out = (float*)d_out;

    const int attn_smem = ATTN_SMEM_FLOATS * (int)sizeof(float);
    cudaFuncSetAttribute(attn_kernel,
                         cudaFuncAttributeMaxDynamicSharedMemorySize, attn_smem);

    // projections (tensor core, cvt fused in loader)
    dim3 pgrid((ROWS + 63) / 64, DM / 64, 3);   // (13, 8, 3)
    proj3_kernel<<<pgrid, 256>>>(queries, keys, values,
                                 Wq, Wk, Wv, bq, bk, bv);

    // fused attention core
    dim3 agrid(GRID_N / QT, NH, BB);            // (14, 8, 4)
    attn_kernel<<<agrid, NT, attn_smem>>>(scale);

    // output projection + gating (tensor core)
    dim3 ogrid((ROWS + 63) / 64, DM / 64, 1);   // (13, 8)
    gemm_out_kernel<<<ogrid, 256>>>(Wo, bo, out);
}

// round 13
// speedup vs baseline: 2.2068x; 1.0481x over previous
#include <cuda_runtime.h>
#include <math_constants.h>
#include <cstdint>

#define BB 4
#define GRID_N 196
#define DM 512
#define NH 8
#define DK 64
#define ROWS (BB * GRID_N)   // 784
#define XS (ROWS * DM)

typedef unsigned long long ull;

// ---- scratch (no allocations allowed) ----
__device__ float g_qsig[XS];
__device__ float g_kp[XS];
__device__ float g_vp[XS];
__device__ float g_img[XS];

__device__ __forceinline__ float sigm_exact(float x) {
    return __fdividef(1.0f, 1.0f + __expf(-x));
}
__device__ __forceinline__ float to_tf32(float x) {
    unsigned r;
    asm("cvt.rna.tf32.f32 %0, %1;" : "=r"(r) : "f"(x));
    return __uint_as_float(r);
}
__device__ __forceinline__ ull pk2(float lo, float hi) {
    ull r;
    asm("mov.b64 %0, {%1, %2};" : "=l"(r) : "f"(lo), "f"(hi));
    return r;
}
__device__ __forceinline__ ull mul2(ull a, ull b) {
    ull d;
    asm("mul.rn.f32x2 %0, %1, %2;" : "=l"(d) : "l"(a), "l"(b));
    return d;
}
__device__ __forceinline__ ull fma2(ull a, ull b, ull c) {
    ull d;
    asm("fma.rn.f32x2 %0, %1, %2, %3;" : "=l"(d) : "l"(a), "l"(b), "l"(c));
    return d;
}
__device__ __forceinline__ float tanh_fast(float x) {
    float t;
    asm("tanh.approx.f32 %0, %1;" : "=f"(t) : "f"(x));
    return t;
}

// ============================================================
// TF32 tensor-core GEMM, fragment-layout smem (layout verified R12).
// out[r,j] = sum_c X[r,c]*W[j,c] + bias[j]   (cvt fused in loader)
// 64x64 CTA tile, 128 thr = 4 warps (2x2), WARP TILE 32x32
// (8 independent HMMA accumulator chains per warp), m16n8k8.
//   A: [kstep][mtile(4)][lane(32)][4]  (kstep stride 516)
//   B: [kstep][ntile(8)][lane(32)][2]  (kstep stride 514)
// ============================================================
#define KC 32
#define NCH (DM / KC)   // 16
#define AF_K 516
#define BF_K 514
#define AF_SZ (4 * AF_K)
#define BF_SZ (4 * BF_K)

__device__ __forceinline__ void mma_tf32(float* d, const unsigned* a, const unsigned* b) {
    asm volatile(
        "mma.sync.aligned.m16n8k8.row.col.f32.tf32.tf32.f32 "
        "{%0,%1,%2,%3}, {%4,%5,%6,%7}, {%8,%9}, {%0,%1,%2,%3};"
        : "+f"(d[0]), "+f"(d[1]), "+f"(d[2]), "+f"(d[3])
        : "r"(a[0]), "r"(a[1]), "r"(a[2]), "r"(a[3]),
          "r"(b[0]), "r"(b[1]));
}

__device__ __forceinline__ void stA(float* dst, float4 v) {
    dst[0]  = to_tf32(v.x); dst[4]  = to_tf32(v.y);
    dst[8]  = to_tf32(v.z); dst[12] = to_tf32(v.w);
}
__device__ __forceinline__ void stB(float* dst, float4 v) {
    dst[0] = to_tf32(v.x); dst[2] = to_tf32(v.y);
    dst[4] = to_tf32(v.z); dst[6] = to_tf32(v.w);
}

template <int EPILOGUE>
__device__ __forceinline__ void gemm_tf32_tile(const float* __restrict__ X,
                                               const float* __restrict__ W,
                                               const float* __restrict__ bias,
                                               float* __restrict__ out,
                                               const float* __restrict__ qsig) {
    __shared__ __align__(16) float Af[2][AF_SZ];
    __shared__ __align__(16) float Bf[2][BF_SZ];

    const int t    = threadIdx.x;
    const int lane = t & 31;
    const int warp = t >> 5;              // 0..3
    const int g    = lane >> 2;           // 0..7
    const int qq   = lane & 3;            // 0..3
    const int wm   = (warp >> 1) * 32;    // 0,32
    const int wn   = (warp & 1) * 32;     // 0,32
    const int r0   = blockIdx.x * 64;
    const int j0   = blockIdx.y * 64;

    // loader geometry: element e = t + i*128 -> (row = e>>3, colgroup = e&7)
    const float* Xp[4]; int adst[4];
    const float* Wp[4]; int bdst[4];
#pragma unroll
    for (int i = 0; i < 4; i++) {
        const int e   = t + i * 128;
        const int row = e >> 3;
        const int cg  = e & 7;
        Xp[i] = &X[min(r0 + row, ROWS - 1) * DM + cg * 4];
        adst[i] = (cg >> 1) * AF_K + (row >> 4) * 128 + (row & 7) * 16
                + ((row >> 3) & 1) + (cg & 1) * 2;
        Wp[i] = &W[(j0 + row) * DM + cg * 4];
        bdst[i] = (cg >> 1) * BF_K + (row >> 3) * 64 + (row & 7) * 8 + (cg & 1);
    }

    float acc[2][4][4];
#pragma unroll
    for (int i = 0; i < 2; i++)
#pragma unroll
        for (int j = 0; j < 4; j++)
#pragma unroll
            for (int e = 0; e < 4; e++) acc[i][j][e] = 0.0f;

    // preload chunk 0 -> buffer 0
#pragma unroll
    for (int i = 0; i < 4; i++) {
        stA(&Af[0][adst[i]], *(const float4*)Xp[i]);
        stB(&Bf[0][bdst[i]], *(const float4*)Wp[i]);
    }
    __syncthreads();

    const int amt = (wm >> 4);   // 0 or 2
    const int bnt = (wn >> 3);   // 0 or 4

    int buf = 0;
#pragma unroll 1
    for (int c = 0; c < NCH; c++) {
        float4 xr[4], wr[4];
        const bool more = (c + 1 < NCH);
        if (more) {
#pragma unroll
            for (int i = 0; i < 4; i++) {
                xr[i] = *(const float4*)(Xp[i] + (c + 1) * KC);
                wr[i] = *(const float4*)(Wp[i] + (c + 1) * KC);
            }
        }
#pragma unroll
        for (int ks = 0; ks < 4; ks++) {
            unsigned a[2][4], b[4][2];
#pragma unroll
            for (int i = 0; i < 2; i++) {
                const float4 av = *(const float4*)&Af[buf][ks * AF_K + (amt + i) * 128 + lane * 4];
                a[i][0] = __float_as_uint(av.x); a[i][1] = __float_as_uint(av.y);
                a[i][2] = __float_as_uint(av.z); a[i][3] = __float_as_uint(av.w);
            }
#pragma unroll
            for (int j = 0; j < 4; j++) {
                const float2 bv = *(const float2*)&Bf[buf][ks * BF_K + (bnt + j) * 64 + lane * 2];
                b[j][0] = __float_as_uint(bv.x); b[j][1] = __float_as_uint(bv.y);
            }
#pragma unroll
            for (int i = 0; i < 2; i++)
#pragma unroll
                for (int j = 0; j < 4; j++)
                    mma_tf32(acc[i][j], a[i], b[j]);
        }
        if (more) {
            const int nb = buf ^ 1;
            __syncthreads();
#pragma unroll
            for (int i = 0; i < 4; i++) {
                stA(&Af[nb][adst[i]], xr[i]);
                stB(&Bf[nb][bdst[i]], wr[i]);
            }
            __syncthreads();
            buf = nb;
        }
    }

    // epilogue: acc[i][j] -> rows r0+wm+16i+{g,g+8}, cols j0+wn+8j+2qq+{0,1}
#pragma unroll
    for (int i = 0; i < 2; i++) {
#pragma unroll
        for (int j = 0; j < 4; j++) {
            const int jc = j0 + wn + j * 8 + 2 * qq;
            const float2 bb = *(const float2*)&bias[jc];
#pragma unroll
            for (int h = 0; h < 2; h++) {
                const int r = r0 + wm + i * 16 + g + h * 8;
                if (r < ROWS) {
                    float ox = acc[i][j][h * 2 + 0] + bb.x;
                    float oy = acc[i][j][h * 2 + 1] + bb.y;
                    if (EPILOGUE == 1) {
                        const float2 qv = *(const float2*)&qsig[r * DM + jc];
                        ox *= sigm_exact(qv.x * ox);
                        oy *= sigm_exact(qv.y * oy);
                    }
                    float2 o; o.x = ox; o.y = oy;
                    *(float2*)&out[r * DM + jc] = o;
                }
            }
        }
    }
}

__global__ void __launch_bounds__(128, 4)
proj3_kernel(const float* Xq, const float* Xk, const float* Xv,
             const float* Wq, const float* Wk, const float* Wv,
             const float* bq, const float* bk, const float* bv) {
    const float* X; const float* W; const float* B; float* O;
    if (blockIdx.z == 0)      { X = Xq; W = Wq; B = bq; O = g_qsig; }
    else if (blockIdx.z == 1) { X = Xk; W = Wk; B = bk; O = g_kp; }
    else                      { X = Xv; W = Wv; B = bv; O = g_vp; }
    gemm_tf32_tile<0>(X, W, B, O, nullptr);
}

__global__ void __launch_bounds__(128, 4)
gemm_out_kernel(const float* __restrict__ Wo, const float* __restrict__ bias,
                float* __restrict__ out) {
    gemm_tf32_tile<1>(g_img, Wo, bias, out, g_qsig);
}

// ============================================================
// Fused attention core — 2 queries per warp, q-tile 14 (7 warps).
// pass 2 uses packed f32x2 FMA; MUFU.TANH sigmoid.
// ============================================================
#define QT 14
#define NW 7
#define NT (NW * 32)
#define KST 66
#define VST 64
#define ATTN_SMEM_FLOATS (GRID_N * KST + GRID_N * VST + QT * 64 + QT * 200)

__global__ void __launch_bounds__(NT)
attn_kernel(const float* __restrict__ scale) {
    extern __shared__ float sm[];
    float* kp = sm;
    float* vp = kp + GRID_N * KST;
    float* qs = vp + GRID_N * VST;
    float* ps = qs + QT * 64;

    const int t  = threadIdx.x;
    const int q0 = blockIdx.x * QT;
    const int h  = blockIdx.y;
    const int b  = blockIdx.z;
    const int hbase = h * DK;

    for (int idx = t; idx < GRID_N * 16; idx += NT) {
        const int s  = idx >> 4;
        const int d4 = (idx & 15) << 2;
        const int g  = (b * GRID_N + s) * DM + hbase + d4;
        const float4 kv = *(const float4*)&g_kp[g];
        const float4 vv = *(const float4*)&g_vp[g];
        float* kd = &kp[s * KST + d4];
        kd[0] = kv.x; kd[1] = kv.y; kd[2] = kv.z; kd[3] = kv.w;
        float* vd = &vp[s * VST + d4];
        vd[0] = vv.x; vd[1] = vv.y; vd[2] = vv.z; vd[3] = vv.w;
    }
    for (int idx = t; idx < QT * 64; idx += NT) {
        const int w = idx >> 6;
        const int d = idx & 63;
        qs[idx] = g_qsig[(b * GRID_N + q0 + w) * DM + hbase + d];
    }
    __syncthreads();

    const int w    = t >> 5;
    const int lane = t & 31;
    const int qA   = q0 + 2 * w;
    const int qB   = qA + 1;
    const float* qrowA = &qs[(2 * w) * 64];
    const float* qrowB = qrowA + 64;

    // ---- pass 1 ----
    const float* rp[7];
#pragma unroll
    for (int j = 0; j < 7; j++) {
        const int k = lane + 32 * j;
        rp[j] = &kp[(k < GRID_N ? k : GRID_N - 1) * KST];
    }
    float attA[7], attB[7];
#pragma unroll
    for (int j = 0; j < 7; j++) { attA[j] = 0.0f; attB[j] = 0.0f; }

#pragma unroll 8
    for (int d = 0; d < 64; d += 2) {
        const float2 qa = *(const float2*)&qrowA[d];
        const float2 qb = *(const float2*)&qrowB[d];
#pragma unroll
        for (int j = 0; j < 7; j++) {
            const float2 kv = *(const float2*)&rp[j][d];
            attA[j] = fmaf(qa.x, kv.x, fmaf(qa.y, kv.y, attA[j]));
            attB[j] = fmaf(qb.x, kv.x, fmaf(qb.y, kv.y, attB[j]));
        }
    }
    const float* srowA = &scale[(h * GRID_N + qA) * GRID_N];
    const float* srowB = &scale[(h * GRID_N + qB) * GRID_N];
#pragma unroll
    for (int j = 0; j < 7; j++) {
        const int k = lane + 32 * j;
        if (k < GRID_N) {
            attA[j] *= srowA[k];
            attB[j] *= srowB[k];
        } else {
            attA[j] = -CUDART_INF_F;
            attB[j] = -CUDART_INF_F;
        }
    }

    // ---- softmax ----
    float mA = attA[0], mB = attB[0];
#pragma unroll
    for (int j = 1; j < 7; j++) { mA = fmaxf(mA, attA[j]); mB = fmaxf(mB, attB[j]); }
#pragma unroll
    for (int off = 16; off > 0; off >>= 1) {
        mA = fmaxf(mA, __shfl_xor_sync(0xFFFFFFFFu, mA, off));
        mB = fmaxf(mB, __shfl_xor_sync(0xFFFFFFFFu, mB, off));
    }
    float sA = 0.0f, sB = 0.0f;
#pragma unroll
    for (int j = 0; j < 7; j++) {
        attA[j] = __expf(attA[j] - mA); sA += attA[j];
        attB[j] = __expf(attB[j] - mB); sB += attB[j];
    }
#pragma unroll
    for (int off = 16; off > 0; off >>= 1) {
        sA += __shfl_xor_sync(0xFFFFFFFFu, sA, off);
        sB += __shfl_xor_sync(0xFFFFFFFFu, sB, off);
    }
    const float invA = __fdividef(1.0f, sA);
    const float invB = __fdividef(1.0f, sB);
    float* pwA = &ps[(2 * w) * 200];
    float* pwB = pwA + 200;
#pragma unroll
    for (int j = 0; j < 7; j++) {
        const int k = lane + 32 * j;
        if (k < GRID_N) {
            pwA[k] = attA[j] * invA;
            pwB[k] = attB[j] * invB;
        }
    }
    __syncwarp();

    // ---- pass 2 ----
    const float qA0 = 0.5f * qrowA[2 * lane], qA1 = 0.5f * qrowA[2 * lane + 1];
    const float qB0 = 0.5f * qrowB[2 * lane], qB1 = 0.5f * qrowB[2 * lane + 1];
    const ull halfs = pk2(0.5f, 0.5f);
    ull accA = pk2(0.0f, 0.0f), accB = accA;
#pragma unroll 4
    for (int k = 0; k < GRID_N; k++) {
        const float pA = pwA[k];
        const float pB = pwB[k];
        const float2 kv = *(const float2*)&kp[k * KST + 2 * lane];
        const ull vv2 = *(const ull*)&vp[k * VST + 2 * lane];
        const float tA0 = tanh_fast(qA0 * kv.x);
        const float tA1 = tanh_fast(qA1 * kv.y);
        const float tB0 = tanh_fast(qB0 * kv.x);
        const float tB1 = tanh_fast(qB1 * kv.y);
        const ull gA = fma2(pk2(tA0, tA1), halfs, halfs);
        const ull gB = fma2(pk2(tB0, tB1), halfs, halfs);
        accA = fma2(pk2(pA, pA), mul2(gA, vv2), accA);
        accB = fma2(pk2(pB, pB), mul2(gB, vv2), accB);
    }
    float aAx, aAy, aBx, aBy;
    asm("mov.b64 {%0, %1}, %2;" : "=f"(aAx), "=f"(aAy) : "l"(accA));
    asm("mov.b64 {%0, %1}, %2;" : "=f"(aBx), "=f"(aBy) : "l"(accB));
    float2 rA; rA.x = aAx; rA.y = aAy;
    float2 rB; rB.x = aBx; rB.y = aBy;
    *(float2*)&g_img[(b * GRID_N + qA) * DM + hbase + 2 * lane] = rA;
    *(float2*)&g_img[(b * GRID_N + qB) * DM + hbase + 2 * lane] = rB;
}

// ============================================================
extern "C" void kernel_launch(void* const* d_in, const int* in_sizes, int n_in,
                              void* d_out, int out_size) {
    (void)in_sizes; (void)n_in; (void)out_size;
    const float* queries = (const float*)d_in[0];
    const float* keys    = (const float*)d_in[1];
    const float* values  = (const float*)d_in[2];
    const float* Wq = (const float*)d_in[3];
    const float* bq = (const float*)d_in[4];
    const float* Wk = (const float*)d_in[5];
    const float* bk = (const float*)d_in[6];
    const float* Wv = (const float*)d_in[7];
    const float* bv = (const float*)d_in[8];
    const float* Wo = (const float*)d_in[9];
    const float* bo = (const float*)d_in[10];
    const float* scale = (const float*)d_in[11];
    float* out = (float*)d_out;

    const int attn_smem = ATTN_SMEM_FLOATS * (int)sizeof(float);
    cudaFuncSetAttribute(attn_kernel,
                         cudaFuncAttributeMaxDynamicSharedMemorySize, attn_smem);

    // projections (tensor core, cvt fused in loader)
    dim3 pgrid((ROWS + 63) / 64, DM / 64, 3);   // (13, 8, 3)
    proj3_kernel<<<pgrid, 128>>>(queries, keys, values,
                                 Wq, Wk, Wv, bq, bk, bv);

    // fused attention core
    dim3 agrid(GRID_N / QT, NH, BB);            // (14, 8, 4)
    attn_kernel<<<agrid, NT, attn_smem>>>(scale);

    // output projection + gating (tensor core)
    dim3 ogrid((ROWS + 63) / 64, DM / 64, 1);   // (13, 8)
    gemm_out_kernel<<<ogrid, 128>>>(Wo, bo, out);
}

// round 15
// speedup vs baseline: 2.5123x; 1.1384x over previous
#include <cuda_runtime.h>
#include <math_constants.h>
#include <cstdint>

#define BB 4
#define GRID_N 196
#define DM 512
#define NH 8
#define DK 64
#define ROWS (BB * GRID_N)   // 784
#define XS (ROWS * DM)

typedef unsigned long long ull;

// ---- scratch (no allocations allowed) ----
__device__ float g_qsig[XS];
__device__ float g_kp[XS];
__device__ float g_vp[XS];
__device__ float g_img[XS];

__device__ __forceinline__ float sigm_exact(float x) {
    return __fdividef(1.0f, 1.0f + __expf(-x));
}
__device__ __forceinline__ float to_tf32(float x) {
    unsigned r;
    asm("cvt.rna.tf32.f32 %0, %1;" : "=r"(r) : "f"(x));
    return __uint_as_float(r);
}
__device__ __forceinline__ float tanh_fast(float x) {
    float t;
    asm("tanh.approx.f32 %0, %1;" : "=f"(t) : "f"(x));
    return t;
}
// pack two f32 into bf16x2 (lo = a, hi = b)
__device__ __forceinline__ unsigned bf2pack(float a, float b) {
    unsigned r;
    asm("cvt.rn.bf16x2.f32 %0, %1, %2;" : "=r"(r) : "f"(b), "f"(a));
    return r;
}
// unpack bf16x2 -> two exact f32
__device__ __forceinline__ float2 bf2f(unsigned p) {
    float2 r;
    r.x = __uint_as_float(p << 16);
    r.y = __uint_as_float(p & 0xFFFF0000u);
    return r;
}

// ============================================================
// TF32 tensor-core GEMM, fragment-layout smem (verified R12/R13).
// 64x64 CTA tile, 128 thr = 4 warps (2x2), warp tile 32x32, m16n8k8.
// ============================================================
#define KC 32
#define NCH (DM / KC)   // 16
#define AF_K 516
#define BF_K 514
#define AF_SZ (4 * AF_K)
#define BF_SZ (4 * BF_K)

__device__ __forceinline__ void mma_tf32(float* d, const unsigned* a, const unsigned* b) {
    asm volatile(
        "mma.sync.aligned.m16n8k8.row.col.f32.tf32.tf32.f32 "
        "{%0,%1,%2,%3}, {%4,%5,%6,%7}, {%8,%9}, {%0,%1,%2,%3};"
        : "+f"(d[0]), "+f"(d[1]), "+f"(d[2]), "+f"(d[3])
        : "r"(a[0]), "r"(a[1]), "r"(a[2]), "r"(a[3]),
          "r"(b[0]), "r"(b[1]));
}

__device__ __forceinline__ void stA(float* dst, float4 v) {
    dst[0]  = to_tf32(v.x); dst[4]  = to_tf32(v.y);
    dst[8]  = to_tf32(v.z); dst[12] = to_tf32(v.w);
}
__device__ __forceinline__ void stB(float* dst, float4 v) {
    dst[0] = to_tf32(v.x); dst[2] = to_tf32(v.y);
    dst[4] = to_tf32(v.z); dst[6] = to_tf32(v.w);
}

template <int EPILOGUE>
__device__ __forceinline__ void gemm_tf32_tile(const float* __restrict__ X,
                                               const float* __restrict__ W,
                                               const float* __restrict__ bias,
                                               float* __restrict__ out,
                                               const float* __restrict__ qsig) {
    __shared__ __align__(16) float Af[2][AF_SZ];
    __shared__ __align__(16) float Bf[2][BF_SZ];

    const int t    = threadIdx.x;
    const int lane = t & 31;
    const int warp = t >> 5;              // 0..3
    const int g    = lane >> 2;           // 0..7
    const int qq   = lane & 3;            // 0..3
    const int wm   = (warp >> 1) * 32;    // 0,32
    const int wn   = (warp & 1) * 32;     // 0,32
    const int r0   = blockIdx.x * 64;
    const int j0   = blockIdx.y * 64;

    const float* Xp[4]; int adst[4];
    const float* Wp[4]; int bdst[4];
#pragma unroll
    for (int i = 0; i < 4; i++) {
        const int e   = t + i * 128;
        const int row = e >> 3;
        const int cg  = e & 7;
        Xp[i] = &X[min(r0 + row, ROWS - 1) * DM + cg * 4];
        adst[i] = (cg >> 1) * AF_K + (row >> 4) * 128 + (row & 7) * 16
                + ((row >> 3) & 1) + (cg & 1) * 2;
        Wp[i] = &W[(j0 + row) * DM + cg * 4];
        bdst[i] = (cg >> 1) * BF_K + (row >> 3) * 64 + (row & 7) * 8 + (cg & 1);
    }

    float acc[2][4][4];
#pragma unroll
    for (int i = 0; i < 2; i++)
#pragma unroll
        for (int j = 0; j < 4; j++)
#pragma unroll
            for (int e = 0; e < 4; e++) acc[i][j][e] = 0.0f;

#pragma unroll
    for (int i = 0; i < 4; i++) {
        stA(&Af[0][adst[i]], *(const float4*)Xp[i]);
        stB(&Bf[0][bdst[i]], *(const float4*)Wp[i]);
    }
    __syncthreads();

    const int amt = (wm >> 4);
    const int bnt = (wn >> 3);

    int buf = 0;
#pragma unroll 1
    for (int c = 0; c < NCH; c++) {
        float4 xr[4], wr[4];
        const bool more = (c + 1 < NCH);
        if (more) {
#pragma unroll
            for (int i = 0; i < 4; i++) {
                xr[i] = *(const float4*)(Xp[i] + (c + 1) * KC);
                wr[i] = *(const float4*)(Wp[i] + (c + 1) * KC);
            }
        }
#pragma unroll
        for (int ks = 0; ks < 4; ks++) {
            unsigned a[2][4], b[4][2];
#pragma unroll
            for (int i = 0; i < 2; i++) {
                const float4 av = *(const float4*)&Af[buf][ks * AF_K + (amt + i) * 128 + lane * 4];
                a[i][0] = __float_as_uint(av.x); a[i][1] = __float_as_uint(av.y);
                a[i][2] = __float_as_uint(av.z); a[i][3] = __float_as_uint(av.w);
            }
#pragma unroll
            for (int j = 0; j < 4; j++) {
                const float2 bv = *(const float2*)&Bf[buf][ks * BF_K + (bnt + j) * 64 + lane * 2];
                b[j][0] = __float_as_uint(bv.x); b[j][1] = __float_as_uint(bv.y);
            }
#pragma unroll
            for (int i = 0; i < 2; i++)
#pragma unroll
                for (int j = 0; j < 4; j++)
                    mma_tf32(acc[i][j], a[i], b[j]);
        }
        if (more) {
            const int nb = buf ^ 1;
            __syncthreads();
#pragma unroll
            for (int i = 0; i < 4; i++) {
                stA(&Af[nb][adst[i]], xr[i]);
                stB(&Bf[nb][bdst[i]], wr[i]);
            }
            __syncthreads();
            buf = nb;
        }
    }

#pragma unroll
    for (int i = 0; i < 2; i++) {
#pragma unroll
        for (int j = 0; j < 4; j++) {
            const int jc = j0 + wn + j * 8 + 2 * qq;
            const float2 bb = *(const float2*)&bias[jc];
#pragma unroll
            for (int h = 0; h < 2; h++) {
                const int r = r0 + wm + i * 16 + g + h * 8;
                if (r < ROWS) {
                    float ox = acc[i][j][h * 2 + 0] + bb.x;
                    float oy = acc[i][j][h * 2 + 1] + bb.y;
                    if (EPILOGUE == 1) {
                        const float2 qv = *(const float2*)&qsig[r * DM + jc];
                        ox *= sigm_exact(qv.x * ox);
                        oy *= sigm_exact(qv.y * oy);
                    }
                    float2 o; o.x = ox; o.y = oy;
                    *(float2*)&out[r * DM + jc] = o;
                }
            }
        }
    }
}

__global__ void __launch_bounds__(128, 4)
proj3_kernel(const float* Xq, const float* Xk, const float* Xv,
             const float* Wq, const float* Wk, const float* Wv,
             const float* bq, const float* bk, const float* bv) {
    const float* X; const float* W; const float* B; float* O;
    if (blockIdx.z == 0)      { X = Xq; W = Wq; B = bq; O = g_qsig; }
    else if (blockIdx.z == 1) { X = Xk; W = Wk; B = bk; O = g_kp; }
    else                      { X = Xv; W = Wv; B = bv; O = g_vp; }
    gemm_tf32_tile<0>(X, W, B, O, nullptr);
}

__global__ void __launch_bounds__(128, 4)
gemm_out_kernel(const float* __restrict__ Wo, const float* __restrict__ bias,
                float* __restrict__ out) {
    gemm_tf32_tile<1>(g_img, Wo, bias, out, g_qsig);
}

// ============================================================
// Fused attention core — bf16 K (logits+gate), f32 V (output path).
// smem 90.8 KB/CTA -> 2 CTA/SM. 2 queries per warp, q-tile 14.
// K row stride 33 words (odd -> conflict-free); V f32 stride 64.
// ============================================================
#define QT 14
#define NW 7
#define NT (NW * 32)
#define KW 33   // u32 words per K row (66 bf16)
#define VST 64  // f32 per V row
#define ATTN_SMEM_BYTES ((GRID_N * KW + GRID_N * VST + QT * 64 + QT * 200) * 4)

__global__ void __launch_bounds__(NT)
attn_kernel(const float* __restrict__ scale) {
    extern __shared__ unsigned smu[];
    unsigned* kp32 = smu;
    float* vp = (float*)(kp32 + GRID_N * KW);
    float* qs = vp + GRID_N * VST;
    float* ps = qs + QT * 64;

    const int t  = threadIdx.x;
    const int q0 = blockIdx.x * QT;
    const int h  = blockIdx.y;
    const int b  = blockIdx.z;
    const int hbase = h * DK;

    // ---- load K (->bf16) and V (f32) head slices ----
    for (int idx = t; idx < GRID_N * 16; idx += NT) {
        const int s  = idx >> 4;
        const int d4 = (idx & 15) << 2;     // 0..60
        const int g  = (b * GRID_N + s) * DM + hbase + d4;
        const float4 kv = *(const float4*)&g_kp[g];
        const float4 vv = *(const float4*)&g_vp[g];
        const int wp = d4 >> 1;
        kp32[s * KW + wp]     = bf2pack(kv.x, kv.y);
        kp32[s * KW + wp + 1] = bf2pack(kv.z, kv.w);
        float* vd = &vp[s * VST + d4];
        vd[0] = vv.x; vd[1] = vv.y; vd[2] = vv.z; vd[3] = vv.w;
    }
    // ---- q rows (f32) ----
    for (int idx = t; idx < QT * 64; idx += NT) {
        const int w = idx >> 6;
        const int d = idx & 63;
        qs[idx] = g_qsig[(b * GRID_N + q0 + w) * DM + hbase + d];
    }
    __syncthreads();

    const int w    = t >> 5;
    const int lane = t & 31;
    const int qA   = q0 + 2 * w;
    const int qB   = qA + 1;
    const float* qrowA = &qs[(2 * w) * 64];
    const float* qrowB = qrowA + 64;

    // ---- pass 1: two dot-product rows, K reads shared ----
    const unsigned* rp[7];
#pragma unroll
    for (int j = 0; j < 7; j++) {
        const int k = lane + 32 * j;
        rp[j] = &kp32[(k < GRID_N ? k : GRID_N - 1) * KW];
    }
    float attA[7], attB[7];
#pragma unroll
    for (int j = 0; j < 7; j++) { attA[j] = 0.0f; attB[j] = 0.0f; }

#pragma unroll 8
    for (int dp = 0; dp < 32; dp++) {
        const float2 qa = *(const float2*)&qrowA[2 * dp];
        const float2 qb = *(const float2*)&qrowB[2 * dp];
#pragma unroll
        for (int j = 0; j < 7; j++) {
            const float2 kf = bf2f(rp[j][dp]);
            attA[j] = fmaf(qa.x, kf.x, fmaf(qa.y, kf.y, attA[j]));
            attB[j] = fmaf(qb.x, kf.x, fmaf(qb.y, kf.y, attB[j]));
        }
    }
    const float* srowA = &scale[(h * GRID_N + qA) * GRID_N];
    const float* srowB = &scale[(h * GRID_N + qB) * GRID_N];
#pragma unroll
    for (int j = 0; j < 7; j++) {
        const int k = lane + 32 * j;
        if (k < GRID_N) {
            attA[j] *= srowA[k];
            attB[j] *= srowB[k];
        } else {
            attA[j] = -CUDART_INF_F;
            attB[j] = -CUDART_INF_F;
        }
    }

    // ---- softmax ----
    float mA = attA[0], mB = attB[0];
#pragma unroll
    for (int j = 1; j < 7; j++) { mA = fmaxf(mA, attA[j]); mB = fmaxf(mB, attB[j]); }
#pragma unroll
    for (int off = 16; off > 0; off >>= 1) {
        mA = fmaxf(mA, __shfl_xor_sync(0xFFFFFFFFu, mA, off));
        mB = fmaxf(mB, __shfl_xor_sync(0xFFFFFFFFu, mB, off));
    }
    float sA = 0.0f, sB = 0.0f;
#pragma unroll
    for (int j = 0; j < 7; j++) {
        attA[j] = __expf(attA[j] - mA); sA += attA[j];
        attB[j] = __expf(attB[j] - mB); sB += attB[j];
    }
#pragma unroll
    for (int off = 16; off > 0; off >>= 1) {
        sA += __shfl_xor_sync(0xFFFFFFFFu, sA, off);
        sB += __shfl_xor_sync(0xFFFFFFFFu, sB, off);
    }
    const float invA = __fdividef(1.0f, sA);
    const float invB = __fdividef(1.0f, sB);
    float* pwA = &ps[(2 * w) * 200];
    float* pwB = pwA + 200;
#pragma unroll
    for (int j = 0; j < 7; j++) {
        const int k = lane + 32 * j;
        if (k < GRID_N) {
            pwA[k] = attA[j] * invA;
            pwB[k] = attB[j] * invB;
        }
    }
    __syncwarp();

    // ---- pass 2: sigmoid-gated PV; bf16 K gate, f32 V ----
    const float qA0 = 0.5f * qrowA[2 * lane], qA1 = 0.5f * qrowA[2 * lane + 1];
    const float qB0 = 0.5f * qrowB[2 * lane], qB1 = 0.5f * qrowB[2 * lane + 1];
    float aAx = 0.f, aAy = 0.f, aBx = 0.f, aBy = 0.f;
#pragma unroll 4
    for (int k = 0; k < GRID_N; k++) {
        const float pA = pwA[k];
        const float pB = pwB[k];
        const float2 kf = bf2f(kp32[k * KW + lane]);
        const float2 vf = *(const float2*)&vp[k * VST + 2 * lane];
        const float tA0 = tanh_fast(qA0 * kf.x);
        const float tA1 = tanh_fast(qA1 * kf.y);
        const float tB0 = tanh_fast(qB0 * kf.x);
        const float tB1 = tanh_fast(qB1 * kf.y);
        const float gA0 = fmaf(0.5f, tA0, 0.5f);
        const float gA1 = fmaf(0.5f, tA1, 0.5f);
        const float gB0 = fmaf(0.5f, tB0, 0.5f);
        const float gB1 = fmaf(0.5f, tB1, 0.5f);
        aAx = fmaf(pA, gA0 * vf.x, aAx);
        aAy = fmaf(pA, gA1 * vf.y, aAy);
        aBx = fmaf(pB, gB0 * vf.x, aBx);
        aBy = fmaf(pB, gB1 * vf.y, aBy);
    }
    float2 rA; rA.x = aAx; rA.y = aAy;
    float2 rB; rB.x = aBx; rB.y = aBy;
    *(float2*)&g_img[(b * GRID_N + qA) * DM + hbase + 2 * lane] = rA;
    *(float2*)&g_img[(b * GRID_N + qB) * DM + hbase + 2 * lane] = rB;
}

// ============================================================
extern "C" void kernel_launch(void* const* d_in, const int* in_sizes, int n_in,
                              void* d_out, int out_size) {
    (void)in_sizes; (void)n_in; (void)out_size;
    const float* queries = (const float*)d_in[0];
    const float* keys    = (const float*)d_in[1];
    const float* values  = (const float*)d_in[2];
    const float* Wq = (const float*)d_in[3];
    const float* bq = (const float*)d_in[4];
    const float* Wk = (const float*)d_in[5];
    const float* bk = (const float*)d_in[6];
    const float* Wv = (const float*)d_in[7];
    const float* bv = (const float*)d_in[8];
    const float* Wo = (const float*)d_in[9];
    const float* bo = (const float*)d_in[10];
    const float* scale = (const float*)d_in[11];
    float* out = (float*)d_out;

    cudaFuncSetAttribute(attn_kernel,
                         cudaFuncAttributeMaxDynamicSharedMemorySize, ATTN_SMEM_BYTES);

    // projections (tensor core, cvt fused in loader)
    dim3 pgrid((ROWS + 63) / 64, DM / 64, 3);   // (13, 8, 3)
    proj3_kernel<<<pgrid, 128>>>(queries, keys, values,
                                 Wq, Wk, Wv, bq, bk, bv);

    // fused attention core
    dim3 agrid(GRID_N / QT, NH, BB);            // (14, 8, 4)
    attn_kernel<<<agrid, NT, ATTN_SMEM_BYTES>>>(scale);

    // output projection + gating (tensor core)
    dim3 ogrid((ROWS + 63) / 64, DM / 64, 1);   // (13, 8)
    gemm_out_kernel<<<ogrid, 128>>>(Wo, bo, out);
}